// round 3
// baseline (speedup 1.0000x reference)
#include <cuda_runtime.h>

#define BATCH  128
#define TIME   256
#define FDIM   512
#define UNITS  1024
#define TP1    (TIME + 1)

#define NBLK_B    128   // 4 batch-tiles x 32 unit-tiles, all co-resident
#define THREADS_B 256

// ---------------------------------------------------------------------------
// Scratch (no cudaMalloc allowed): double-buffered recurrent state, 1 MB.
// ---------------------------------------------------------------------------
__device__ float    g_S[2][BATCH * UNITS];
__device__ unsigned g_bar_count;   // zero-initialized
__device__ unsigned g_bar_gen;     // monotonically increasing across replays

// ---------------------------------------------------------------------------
// Software grid barrier (cooperative-groups pattern, graph-capture safe).
// All 128 blocks are guaranteed co-resident (1 block/SM, 152 SMs).
// ---------------------------------------------------------------------------
__device__ __forceinline__ void grid_barrier(unsigned nblocks, unsigned& gen) {
    __syncthreads();
    if (threadIdx.x == 0) {
        __threadfence();  // cumulative: publishes whole block's prior stores
        unsigned old = atomicAdd(&g_bar_count, 1u);
        if (old == nblocks - 1u) {
            g_bar_count = 0u;          // safe: everyone is spinning on gen
            __threadfence();
            atomicAdd(&g_bar_gen, 1u); // release
        } else {
            while (*(volatile unsigned*)&g_bar_gen == gen) { __nanosleep(40); }
        }
        __threadfence();  // acquire side
    }
    __syncthreads();
    gen += 1u;
}

// ---------------------------------------------------------------------------
// Kernel A: h = inputs @ R + bias, written into out[b, t, :] (t < TIME).
// Tiled SGEMM: block tile 64x64, BK=16, thread tile 4x4, 256 threads.
// ---------------------------------------------------------------------------
__global__ void __launch_bounds__(256) hin_gemm_kernel(
    const float* __restrict__ X,     // [BATCH*TIME, FDIM]
    const float* __restrict__ R,     // [FDIM, UNITS]
    const float* __restrict__ bias,  // [UNITS]
    float* __restrict__ out)         // [BATCH, TP1, UNITS]
{
    __shared__ float As[16][68];   // [k][m], padded
    __shared__ float Bs[16][64];   // [k][n]

    const int tid  = threadIdx.x;
    const int tx   = tid & 15;   // n quad index
    const int ty   = tid >> 4;   // m quad index
    const int row0 = blockIdx.y * 64;
    const int col0 = blockIdx.x * 64;

    // A-load mapping: thread -> (row li, k-quad lj)
    const int li = tid >> 2;          // 0..63
    const int lj = (tid & 3) * 4;     // 0,4,8,12
    // B-load mapping: thread -> (k-row rj, col ri)
    const int rj = tid >> 4;          // 0..15
    const int ri = (tid & 15) * 4;    // 0..60

    float acc[4][4];
    #pragma unroll
    for (int i = 0; i < 4; i++)
        #pragma unroll
        for (int j = 0; j < 4; j++) acc[i][j] = 0.0f;

    for (int k0 = 0; k0 < FDIM; k0 += 16) {
        float4 a = *(const float4*)(X + (size_t)(row0 + li) * FDIM + k0 + lj);
        float4 b = *(const float4*)(R + (size_t)(k0 + rj) * UNITS + col0 + ri);
        As[lj + 0][li] = a.x;
        As[lj + 1][li] = a.y;
        As[lj + 2][li] = a.z;
        As[lj + 3][li] = a.w;
        *(float4*)(&Bs[rj][ri]) = b;
        __syncthreads();

        #pragma unroll
        for (int k = 0; k < 16; k++) {
            float4 av = *(const float4*)(&As[k][ty * 4]);
            float4 bv = *(const float4*)(&Bs[k][tx * 4]);
            acc[0][0] = fmaf(av.x, bv.x, acc[0][0]);
            acc[0][1] = fmaf(av.x, bv.y, acc[0][1]);
            acc[0][2] = fmaf(av.x, bv.z, acc[0][2]);
            acc[0][3] = fmaf(av.x, bv.w, acc[0][3]);
            acc[1][0] = fmaf(av.y, bv.x, acc[1][0]);
            acc[1][1] = fmaf(av.y, bv.y, acc[1][1]);
            acc[1][2] = fmaf(av.y, bv.z, acc[1][2]);
            acc[1][3] = fmaf(av.y, bv.w, acc[1][3]);
            acc[2][0] = fmaf(av.z, bv.x, acc[2][0]);
            acc[2][1] = fmaf(av.z, bv.y, acc[2][1]);
            acc[2][2] = fmaf(av.z, bv.z, acc[2][2]);
            acc[2][3] = fmaf(av.z, bv.w, acc[2][3]);
            acc[3][0] = fmaf(av.w, bv.x, acc[3][0]);
            acc[3][1] = fmaf(av.w, bv.y, acc[3][1]);
            acc[3][2] = fmaf(av.w, bv.z, acc[3][2]);
            acc[3][3] = fmaf(av.w, bv.w, acc[3][3]);
        }
        __syncthreads();
    }

    float4 bv = *(const float4*)(bias + col0 + tx * 4);
    #pragma unroll
    for (int i = 0; i < 4; i++) {
        int m    = row0 + ty * 4 + i;
        int bidx = m >> 8;         // TIME == 256
        int tt   = m & 255;
        float* op = out + ((size_t)(bidx * TP1 + tt)) * UNITS + col0 + tx * 4;
        float4 v;
        v.x = acc[i][0] + bv.x;
        v.y = acc[i][1] + bv.y;
        v.z = acc[i][2] + bv.z;
        v.w = acc[i][3] + bv.w;
        *(float4*)op = v;
    }
}

// ---------------------------------------------------------------------------
// Kernel B: persistent recurrence.
//   Block (bb, ub): batch rows [bb*32, bb*32+32), unit cols [ub*32, ub*32+32).
//   Keeps its W[:, u-slice] (1024x32, 128 KB) in shared for all 256 steps.
//   Per step: stage state k-chunks into shared, FFMA 32x32x1024 tile,
//   tanh epilogue writes out[b,t,:] (overwriting h), writes next state,
//   accumulates exp(s) in registers, grid barrier.
// ---------------------------------------------------------------------------
__global__ void __launch_bounds__(THREADS_B) recurrent_kernel(
    const float* __restrict__ W,    // [UNITS, UNITS]
    const float* __restrict__ x0,   // [UNITS]
    float* __restrict__ out)        // [BATCH, TP1, UNITS]
{
    extern __shared__ float sm[];
    float* Ws = sm;                  // [1024][32]  W slice
    float* sS = sm + UNITS * 32;     // [32][68]    staged state chunk (b-major)

    const int tid = threadIdx.x;
    const int ub  = blockIdx.x & 31;
    const int bb  = blockIdx.x >> 5;
    const int u0  = ub * 32;
    const int b0  = bb * 32;
    const int tx  = tid & 15;        // unit pair
    const int ty  = tid >> 4;        // batch pair
    const int ul  = tx * 2;
    const int bl  = ty * 2;

    // Load W slice into shared (once, reused 256 steps).
    {
        const int q = (tid & 7) * 4;
        for (int k = tid >> 3; k < UNITS; k += 32) {
            *(float4*)(Ws + k * 32 + q) =
                *(const float4*)(W + (size_t)k * UNITS + u0 + q);
        }
    }

    // Initialize state buffer 0 with x0 (this block's tile; barrier makes it global).
    {
        float v0 = x0[u0 + ul];
        float v1 = x0[u0 + ul + 1];
        g_S[0][(b0 + bl) * UNITS + u0 + ul]         = v0;
        g_S[0][(b0 + bl) * UNITS + u0 + ul + 1]     = v1;
        g_S[0][(b0 + bl + 1) * UNITS + u0 + ul]     = v0;
        g_S[0][(b0 + bl + 1) * UNITS + u0 + ul + 1] = v1;
    }

    unsigned gen = *(volatile unsigned*)&g_bar_gen;
    grid_barrier(NBLK_B, gen);   // also covers the Ws shared-memory fill

    float es00 = 0.0f, es01 = 0.0f, es10 = 0.0f, es11 = 0.0f;
    int cur = 0;

    const int blr = tid >> 3;          // 0..31: state row staged by this thread
    const int kq8 = (tid & 7) * 8;     // k offset within chunk

    for (int t = 0; t < TIME; t++) {
        float a00 = 0.0f, a01 = 0.0f, a10 = 0.0f, a11 = 0.0f;
        const float* Sc = g_S[cur];

        for (int kc = 0; kc < UNITS; kc += 64) {
            // Stage Sc[b0..b0+31][kc..kc+63] into sS (L2-only loads: L1 is stale
            // across steps because other SMs rewrite the state buffers).
            const float* src = Sc + (size_t)(b0 + blr) * UNITS + kc + kq8;
            float4 v0 = __ldcg((const float4*)src);
            float4 v1 = __ldcg((const float4*)(src + 4));
            *(float4*)(sS + blr * 68 + kq8)     = v0;
            *(float4*)(sS + blr * 68 + kq8 + 4) = v1;
            __syncthreads();

            const float* wp  = Ws + kc * 32 + ul;
            const float* sp0 = sS + bl * 68;
            const float* sp1 = sS + (bl + 1) * 68;
            #pragma unroll 8
            for (int kk = 0; kk < 64; kk++) {
                float2 w = *(const float2*)(wp + kk * 32);
                float s0 = sp0[kk];
                float s1 = sp1[kk];
                a00 = fmaf(s0, w.x, a00);
                a01 = fmaf(s0, w.y, a01);
                a10 = fmaf(s1, w.x, a10);
                a11 = fmaf(s1, w.y, a11);
            }
            __syncthreads();
        }

        // Epilogue: s = tanh(h + acc); write out (overwrite h slot), next state,
        // and accumulate exp(s) in registers.
        float* o0 = out + ((size_t)((b0 + bl) * TP1 + t)) * UNITS + u0 + ul;
        float* o1 = o0 + (size_t)TP1 * UNITS;
        float s00 = tanhf(o0[0] + a00);
        float s01 = tanhf(o0[1] + a01);
        float s10 = tanhf(o1[0] + a10);
        float s11 = tanhf(o1[1] + a11);
        o0[0] = s00; o0[1] = s01;
        o1[0] = s10; o1[1] = s11;

        float* n0 = &g_S[cur ^ 1][(b0 + bl) * UNITS + u0 + ul];
        float* n1 = n0 + UNITS;
        n0[0] = s00; n0[1] = s01;
        n1[0] = s10; n1[1] = s11;

        es00 += expf(s00);
        es01 += expf(s01);
        es10 += expf(s10);
        es11 += expf(s11);

        grid_barrier(NBLK_B, gen);
        cur ^= 1;
    }

    // Terminal row: (1/beta) * log(tanh(mean_t exp(beta*s))), beta = 1.
    const float inv = 1.0f / (float)TIME;
    float* o0 = out + ((size_t)((b0 + bl) * TP1 + TIME)) * UNITS + u0 + ul;
    float* o1 = o0 + (size_t)TP1 * UNITS;
    o0[0] = logf(tanhf(es00 * inv));
    o0[1] = logf(tanhf(es01 * inv));
    o1[0] = logf(tanhf(es10 * inv));
    o1[1] = logf(tanhf(es11 * inv));
}

// ---------------------------------------------------------------------------
// Launch
// ---------------------------------------------------------------------------
extern "C" void kernel_launch(void* const* d_in, const int* in_sizes, int n_in,
                              void* d_out, int out_size) {
    const float* X    = (const float*)d_in[0];  // inputs [128,256,512]
    const float* R    = (const float*)d_in[1];  // [512,1024]
    const float* W    = (const float*)d_in[2];  // [1024,1024]
    const float* bias = (const float*)d_in[3];  // [1024]
    const float* x0   = (const float*)d_in[4];  // [1024]
    float* out = (float*)d_out;                 // [128,257,1024]

    (void)in_sizes; (void)n_in; (void)out_size;

    dim3 gridA(UNITS / 64, (BATCH * TIME) / 64);
    hin_gemm_kernel<<<gridA, 256>>>(X, R, bias, out);

    const int smemB = (UNITS * 32 + 32 * 68) * (int)sizeof(float);  // 139776 B
    cudaFuncSetAttribute(recurrent_kernel,
                         cudaFuncAttributeMaxDynamicSharedMemorySize, smemB);
    recurrent_kernel<<<NBLK_B, THREADS_B, smemB>>>(W, x0, out);
}

// round 4
// speedup vs baseline: 1.0240x; 1.0240x over previous
#include <cuda_runtime.h>

#define BATCH  128
#define TIME   256
#define FDIM   512
#define UNITS  1024
#define TP1    257

#define NBLK   128      // 4 batch-tiles x 32 unit-tiles
#define CHUNK  128      // k per staged chunk
#define NCHUNK (UNITS / CHUNK)
#define CHSZ   (CHUNK * 64)   // duplicated chunk: 128 k x 32 batch x 2 copies

// ---------------------------------------------------------------------------
// Scratch: double-buffered state (1 MB) + per-group barrier counters.
// ---------------------------------------------------------------------------
__device__ float    g_S[2][BATCH * UNITS];
__device__ unsigned g_cnt[4];
__device__ unsigned g_gen[4];

// ---------------------------------------------------------------------------
// Packed fp32x2 FMA (Blackwell double-rate FP32; ptxas won't emit from C++).
// ---------------------------------------------------------------------------
__device__ __forceinline__ void ffma2(unsigned long long& d,
                                      unsigned long long a,
                                      unsigned long long b) {
    asm("fma.rn.f32x2 %0, %1, %2, %0;" : "+l"(d) : "l"(a), "l"(b));
}
__device__ __forceinline__ float2 u2f2(unsigned long long v) {
    float2 f;
    f.x = __uint_as_float((unsigned)(v & 0xffffffffu));
    f.y = __uint_as_float((unsigned)(v >> 32));
    return f;
}

// ---------------------------------------------------------------------------
// Barrier among the 32 blocks of one batch-tile group.
// ---------------------------------------------------------------------------
__device__ __forceinline__ void group_barrier(int g, unsigned& gen) {
    __syncthreads();
    if (threadIdx.x == 0) {
        __threadfence();
        unsigned old = atomicAdd(&g_cnt[g], 1u);
        if (old == 31u) {
            g_cnt[g] = 0u;
            __threadfence();
            atomicAdd(&g_gen[g], 1u);
        } else {
            while (*(volatile unsigned*)&g_gen[g] == gen) { __nanosleep(32); }
        }
        __threadfence();
    }
    __syncthreads();
    gen += 1u;
}

// ---------------------------------------------------------------------------
// Kernel A: h = inputs @ R + bias -> out[b, t, :].  64x64 tile, BK=16,
// 256 threads, 4x4 thread tile, n-packed FFMA2 with duplicated A in shared.
// ---------------------------------------------------------------------------
#define ASTRIDE 132   // floats per k-row of duplicated A (pad for STS conflicts)

__global__ void __launch_bounds__(256) hin_gemm_kernel(
    const float* __restrict__ X,     // [BATCH*TIME, FDIM]
    const float* __restrict__ R,     // [FDIM, UNITS]
    const float* __restrict__ bias,  // [UNITS]
    float* __restrict__ out)         // [BATCH, TP1, UNITS]
{
    __shared__ float Asd[16 * ASTRIDE];  // [k][2m] duplicated
    __shared__ float Bs[16 * 64];        // [k][n]

    const int tid  = threadIdx.x;
    const int tx   = tid & 15;    // n quad
    const int ty   = tid >> 4;    // m quad
    const int row0 = blockIdx.y * 64;
    const int col0 = blockIdx.x * 64;

    const int li = tid >> 2;         // 0..63 A row
    const int lj = (tid & 3) * 4;    // k offset
    const int rj = tid >> 4;         // 0..15 B k-row
    const int ri = (tid & 15) * 4;   // B col

    unsigned long long cc[4][2];
    #pragma unroll
    for (int i = 0; i < 4; i++) { cc[i][0] = 0ULL; cc[i][1] = 0ULL; }

    for (int k0 = 0; k0 < FDIM; k0 += 16) {
        float4 a = *(const float4*)(X + (size_t)(row0 + li) * FDIM + k0 + lj);
        float4 b = *(const float4*)(R + (size_t)(k0 + rj) * UNITS + col0 + ri);
        *(float2*)(Asd + (lj + 0) * ASTRIDE + li * 2) = make_float2(a.x, a.x);
        *(float2*)(Asd + (lj + 1) * ASTRIDE + li * 2) = make_float2(a.y, a.y);
        *(float2*)(Asd + (lj + 2) * ASTRIDE + li * 2) = make_float2(a.z, a.z);
        *(float2*)(Asd + (lj + 3) * ASTRIDE + li * 2) = make_float2(a.w, a.w);
        *(float4*)(Bs + rj * 64 + ri) = b;
        __syncthreads();

        #pragma unroll
        for (int k = 0; k < 16; k++) {
            ulonglong2 a01 = *(const ulonglong2*)(Asd + k * ASTRIDE + ty * 8);
            ulonglong2 a23 = *(const ulonglong2*)(Asd + k * ASTRIDE + ty * 8 + 4);
            ulonglong2 bv  = *(const ulonglong2*)(Bs + k * 64 + tx * 4);
            ffma2(cc[0][0], a01.x, bv.x); ffma2(cc[0][1], a01.x, bv.y);
            ffma2(cc[1][0], a01.y, bv.x); ffma2(cc[1][1], a01.y, bv.y);
            ffma2(cc[2][0], a23.x, bv.x); ffma2(cc[2][1], a23.x, bv.y);
            ffma2(cc[3][0], a23.y, bv.x); ffma2(cc[3][1], a23.y, bv.y);
        }
        __syncthreads();
    }

    float4 bv = *(const float4*)(bias + col0 + tx * 4);
    #pragma unroll
    for (int i = 0; i < 4; i++) {
        int m    = row0 + ty * 4 + i;
        int bidx = m >> 8;     // TIME == 256
        int tt   = m & 255;
        float2 lo = u2f2(cc[i][0]);
        float2 hi = u2f2(cc[i][1]);
        float4 v;
        v.x = lo.x + bv.x; v.y = lo.y + bv.y;
        v.z = hi.x + bv.z; v.w = hi.y + bv.w;
        *(float4*)(out + ((size_t)(bidx * TP1 + tt)) * UNITS + col0 + tx * 4) = v;
    }
}

// ---------------------------------------------------------------------------
// Kernel B helpers: staged state (k-major, value-duplicated for f32x2).
// ---------------------------------------------------------------------------
__device__ __forceinline__ void stage_load(const float* __restrict__ src,
                                           float4 (&pf)[8]) {
    #pragma unroll
    for (int q = 0; q < 8; q++)
        pf[q] = __ldcg((const float4*)src + q);
}
__device__ __forceinline__ void stage_store(float* __restrict__ dst,
                                            const float4 (&pf)[8],
                                            int sko, int sb) {
    #pragma unroll
    for (int q = 0; q < 8; q++) {
        const float* v = (const float*)&pf[q];
        #pragma unroll
        for (int j = 0; j < 4; j++) {
            *(float2*)(dst + (sko + q * 4 + j) * 64 + sb * 2)
                = make_float2(v[j], v[j]);
        }
    }
}

// ---------------------------------------------------------------------------
// Kernel B: persistent recurrence. Block (bb, ub): batch rows [bb*32, +32),
// units [ub*32, +32). W slice (1024x32, 128KB) resident in shared all steps.
// 128 threads, thread tile 4 units x 2 batches, all-FFMA2 inner loop.
// ---------------------------------------------------------------------------
__global__ void __launch_bounds__(128) recurrent_kernel(
    const float* __restrict__ W,    // [UNITS, UNITS]
    const float* __restrict__ x0,   // [UNITS]
    float* __restrict__ out)        // [BATCH, TP1, UNITS]
{
    extern __shared__ float sm[];
    float* Ws = sm;                  // [1024][32]
    float* sS = sm + UNITS * 32;     // 2 x [CHUNK][64] duplicated state

    const int tid = threadIdx.x;
    const int ub  = blockIdx.x & 31;
    const int bb  = blockIdx.x >> 5;
    const int u0  = ub * 32;
    const int b0  = bb * 32;
    const int ug  = tid & 7;         // unit group (4 units)
    const int bp  = tid >> 3;        // 0..15 batch pair
    const int sb  = tid & 31;        // staging: batch row
    const int sko = (tid >> 5) * 32; // staging: k offset

    // Fill W slice (reused 256 steps).
    {
        const int q = (tid & 7) * 4;
        for (int k = tid >> 3; k < UNITS; k += 16) {
            *(float4*)(Ws + k * 32 + q) =
                *(const float4*)(W + (size_t)k * UNITS + u0 + q);
        }
    }

    // Init state buffer 0 with x0 (this block's tile).
    {
        float4 xv = *(const float4*)(x0 + u0 + ug * 4);
        int gb = b0 + bp * 2;
        *(float4*)(&g_S[0][(size_t)gb * UNITS + u0 + ug * 4])       = xv;
        *(float4*)(&g_S[0][(size_t)(gb + 1) * UNITS + u0 + ug * 4]) = xv;
    }

    unsigned gen = *(volatile unsigned*)&g_gen[bb];
    group_barrier(bb, gen);

    float es[8];
    #pragma unroll
    for (int i = 0; i < 8; i++) es[i] = 0.0f;

    int cur = 0;
    float4 pf[8];

    // Preload chunk 0 of step 0.
    stage_load(g_S[cur] + (size_t)(b0 + sb) * UNITS + sko, pf);
    stage_store(sS, pf, sko, sb);
    __syncthreads();

    for (int t = 0; t < TIME; t++) {
        const float* Sc = g_S[cur];
        unsigned long long a0 = 0ULL, a1 = 0ULL, a2 = 0ULL, a3 = 0ULL;

        for (int c = 0; c < NCHUNK; c++) {
            if (c + 1 < NCHUNK)
                stage_load(Sc + (size_t)(b0 + sb) * UNITS + (c + 1) * CHUNK + sko, pf);

            const float* wb = Ws + (c * CHUNK) * 32 + ug * 4;
            const float* db = sS + (c & 1) * CHSZ + bp * 4;
            #pragma unroll 16
            for (int kk = 0; kk < CHUNK; kk++) {
                ulonglong2 w = *(const ulonglong2*)(wb + kk * 32);
                ulonglong2 s = *(const ulonglong2*)(db + kk * 64);
                ffma2(a0, w.x, s.x);   // units u0..u0+1, batch gb
                ffma2(a1, w.y, s.x);   // units u0+2..u0+3, batch gb
                ffma2(a2, w.x, s.y);   // batch gb+1
                ffma2(a3, w.y, s.y);
            }

            if (c + 1 < NCHUNK)
                stage_store(sS + ((c + 1) & 1) * CHSZ, pf, sko, sb);
            __syncthreads();
        }

        // Epilogue: s = tanh(h + acc) -> out (overwrite h), next state, exp acc.
        float2 f0 = u2f2(a0), f1 = u2f2(a1), f2 = u2f2(a2), f3 = u2f2(a3);
        const int gb = b0 + bp * 2;
        float* op0 = out + ((size_t)gb * TP1 + t) * UNITS + u0 + ug * 4;
        float* op1 = op0 + (size_t)TP1 * UNITS;
        float4 h0 = *(const float4*)op0;
        float4 h1 = *(const float4*)op1;
        float4 s0, s1;
        s0.x = tanhf(h0.x + f0.x); s0.y = tanhf(h0.y + f0.y);
        s0.z = tanhf(h0.z + f1.x); s0.w = tanhf(h0.w + f1.y);
        s1.x = tanhf(h1.x + f2.x); s1.y = tanhf(h1.y + f2.y);
        s1.z = tanhf(h1.z + f3.x); s1.w = tanhf(h1.w + f3.y);
        *(float4*)op0 = s0;
        *(float4*)op1 = s1;

        float* n0 = &g_S[cur ^ 1][(size_t)gb * UNITS + u0 + ug * 4];
        *(float4*)n0           = s0;
        *(float4*)(n0 + UNITS) = s1;

        es[0] += __expf(s0.x); es[1] += __expf(s0.y);
        es[2] += __expf(s0.z); es[3] += __expf(s0.w);
        es[4] += __expf(s1.x); es[5] += __expf(s1.y);
        es[6] += __expf(s1.z); es[7] += __expf(s1.w);

        cur ^= 1;
        if (t + 1 < TIME) {
            group_barrier(bb, gen);
            stage_load(g_S[cur] + (size_t)(b0 + sb) * UNITS + sko, pf);
            stage_store(sS, pf, sko, sb);
            __syncthreads();
        }
    }

    // Terminal: (1/beta) * log(tanh(mean_t exp(beta*s))), beta = 1.
    const float inv = 1.0f / (float)TIME;
    const int gb = b0 + bp * 2;
    float* op0 = out + ((size_t)gb * TP1 + TIME) * UNITS + u0 + ug * 4;
    float* op1 = op0 + (size_t)TP1 * UNITS;
    float4 t0, t1;
    t0.x = logf(tanhf(es[0] * inv)); t0.y = logf(tanhf(es[1] * inv));
    t0.z = logf(tanhf(es[2] * inv)); t0.w = logf(tanhf(es[3] * inv));
    t1.x = logf(tanhf(es[4] * inv)); t1.y = logf(tanhf(es[5] * inv));
    t1.z = logf(tanhf(es[6] * inv)); t1.w = logf(tanhf(es[7] * inv));
    *(float4*)op0 = t0;
    *(float4*)op1 = t1;
}

// ---------------------------------------------------------------------------
// Launch
// ---------------------------------------------------------------------------
extern "C" void kernel_launch(void* const* d_in, const int* in_sizes, int n_in,
                              void* d_out, int out_size) {
    const float* X    = (const float*)d_in[0];  // [128,256,512]
    const float* R    = (const float*)d_in[1];  // [512,1024]
    const float* W    = (const float*)d_in[2];  // [1024,1024]
    const float* bias = (const float*)d_in[3];  // [1024]
    const float* x0   = (const float*)d_in[4];  // [1024]
    float* out = (float*)d_out;                 // [128,257,1024]

    (void)in_sizes; (void)n_in; (void)out_size;

    dim3 gridA(UNITS / 64, (BATCH * TIME) / 64);
    hin_gemm_kernel<<<gridA, 256>>>(X, R, bias, out);

    const int smemB = (UNITS * 32 + 2 * CHSZ) * (int)sizeof(float);  // 196608 B
    cudaFuncSetAttribute(recurrent_kernel,
                         cudaFuncAttributeMaxDynamicSharedMemorySize, smemB);
    recurrent_kernel<<<NBLK, 128, smemB>>>(W, x0, out);
}

// round 5
// speedup vs baseline: 1.0431x; 1.0187x over previous
#include <cuda_runtime.h>

#define BATCH  128
#define TIME   256
#define FDIM   512
#define UNITS  1024
#define TP1    257

#define NBLK    128     // 4 batch-groups x 32 unit-tiles
#define CHUNKB  64      // k per staged chunk (per half)
#define HALFK   512
#define NCH     (HALFK / CHUNKB)   // 8 chunks per half
#define DUPSZ   (CHUNKB * 64)      // duplicated chunk floats (64 k x 32 b x 2)

// ---------------------------------------------------------------------------
// Scratch: double-buffered state (1 MB) + per-group barrier counters.
// ---------------------------------------------------------------------------
__device__ float    g_S[2][BATCH * UNITS];
__device__ unsigned g_cnt[4];
__device__ unsigned g_gen[4];

// ---------------------------------------------------------------------------
// Packed fp32x2 ops (Blackwell double-rate FP32; ptxas won't emit from C++).
// ---------------------------------------------------------------------------
__device__ __forceinline__ void ffma2(unsigned long long& d,
                                      unsigned long long a,
                                      unsigned long long b) {
    asm("fma.rn.f32x2 %0, %1, %2, %0;" : "+l"(d) : "l"(a), "l"(b));
}
__device__ __forceinline__ void fadd2(unsigned long long& d,
                                      unsigned long long a) {
    asm("add.rn.f32x2 %0, %0, %1;" : "+l"(d) : "l"(a));
}
__device__ __forceinline__ float2 u2f2(unsigned long long v) {
    float2 f;
    f.x = __uint_as_float((unsigned)(v & 0xffffffffu));
    f.y = __uint_as_float((unsigned)(v >> 32));
    return f;
}

// ---------------------------------------------------------------------------
// Barrier among the 32 blocks of one batch group.
// ---------------------------------------------------------------------------
__device__ __forceinline__ void group_barrier(int g, unsigned& gen) {
    __syncthreads();
    if (threadIdx.x == 0) {
        __threadfence();
        unsigned old = atomicAdd(&g_cnt[g], 1u);
        if (old == 31u) {
            g_cnt[g] = 0u;
            __threadfence();
            atomicAdd(&g_gen[g], 1u);
        } else {
            while (*(volatile unsigned*)&g_gen[g] == gen) { __nanosleep(20); }
        }
        __threadfence();
    }
    __syncthreads();
    gen += 1u;
}

// ---------------------------------------------------------------------------
// Kernel A: h = inputs @ R + bias -> out[b, t, :].  64x64 tile, BK=16,
// 256 threads, 4x4 thread tile, FFMA2, register double-buffered global loads.
// ---------------------------------------------------------------------------
#define ASTRIDE 132

__global__ void __launch_bounds__(256) hin_gemm_kernel(
    const float* __restrict__ X,     // [BATCH*TIME, FDIM]
    const float* __restrict__ R,     // [FDIM, UNITS]
    const float* __restrict__ bias,  // [UNITS]
    float* __restrict__ out)         // [BATCH, TP1, UNITS]
{
    __shared__ float Asd[16 * ASTRIDE];  // [k][2m] duplicated
    __shared__ float Bs[16 * 64];        // [k][n]

    const int tid  = threadIdx.x;
    const int tx   = tid & 15;
    const int ty   = tid >> 4;
    const int row0 = blockIdx.y * 64;
    const int col0 = blockIdx.x * 64;

    const int li = tid >> 2;
    const int lj = (tid & 3) * 4;
    const int rj = tid >> 4;
    const int ri = (tid & 15) * 4;

    unsigned long long cc[4][2];
    #pragma unroll
    for (int i = 0; i < 4; i++) { cc[i][0] = 0ULL; cc[i][1] = 0ULL; }

    float4 a = *(const float4*)(X + (size_t)(row0 + li) * FDIM + lj);
    float4 b = *(const float4*)(R + (size_t)rj * UNITS + col0 + ri);

    for (int k0 = 0; k0 < FDIM; k0 += 16) {
        *(float2*)(Asd + (lj + 0) * ASTRIDE + li * 2) = make_float2(a.x, a.x);
        *(float2*)(Asd + (lj + 1) * ASTRIDE + li * 2) = make_float2(a.y, a.y);
        *(float2*)(Asd + (lj + 2) * ASTRIDE + li * 2) = make_float2(a.z, a.z);
        *(float2*)(Asd + (lj + 3) * ASTRIDE + li * 2) = make_float2(a.w, a.w);
        *(float4*)(Bs + rj * 64 + ri) = b;
        __syncthreads();

        if (k0 + 16 < FDIM) {
            a = *(const float4*)(X + (size_t)(row0 + li) * FDIM + k0 + 16 + lj);
            b = *(const float4*)(R + (size_t)(k0 + 16 + rj) * UNITS + col0 + ri);
        }

        #pragma unroll
        for (int k = 0; k < 16; k++) {
            ulonglong2 a01 = *(const ulonglong2*)(Asd + k * ASTRIDE + ty * 8);
            ulonglong2 a23 = *(const ulonglong2*)(Asd + k * ASTRIDE + ty * 8 + 4);
            ulonglong2 bv  = *(const ulonglong2*)(Bs + k * 64 + tx * 4);
            ffma2(cc[0][0], a01.x, bv.x); ffma2(cc[0][1], a01.x, bv.y);
            ffma2(cc[1][0], a01.y, bv.x); ffma2(cc[1][1], a01.y, bv.y);
            ffma2(cc[2][0], a23.x, bv.x); ffma2(cc[2][1], a23.x, bv.y);
            ffma2(cc[3][0], a23.y, bv.x); ffma2(cc[3][1], a23.y, bv.y);
        }
        __syncthreads();
    }

    float4 bv = *(const float4*)(bias + col0 + tx * 4);
    #pragma unroll
    for (int i = 0; i < 4; i++) {
        int m    = row0 + ty * 4 + i;
        int bidx = m >> 8;
        int tt   = m & 255;
        float2 lo = u2f2(cc[i][0]);
        float2 hi = u2f2(cc[i][1]);
        float4 v;
        v.x = lo.x + bv.x; v.y = lo.y + bv.y;
        v.z = hi.x + bv.z; v.w = hi.y + bv.w;
        *(float4*)(out + ((size_t)(bidx * TP1 + tt)) * UNITS + col0 + tx * 4) = v;
    }
}

// ---------------------------------------------------------------------------
// Kernel B: persistent recurrence. Block (bb, ub): batches [bb*32,+32),
// units [ub*32,+32). W slice (1024x32, 128KB) resident in shared.
// 256 threads, 2-way k-split (warps 0-3: k<512, warps 4-7: k>=512),
// thread tile 4 units x 2 batches, all-FFMA2, double-buffered staging.
// ---------------------------------------------------------------------------
__global__ void __launch_bounds__(256) recurrent_kernel(
    const float* __restrict__ W,    // [UNITS, UNITS]
    const float* __restrict__ x0,   // [UNITS]
    float* __restrict__ out)        // [BATCH, TP1, UNITS]
{
    extern __shared__ float sm[];
    float* Ws = sm;                        // [1024][32]
    float* sS = sm + UNITS * 32;           // 2 halves x 2 bufs x DUPSZ

    const int tid  = threadIdx.x;
    const int ub   = blockIdx.x & 31;
    const int bb   = blockIdx.x >> 5;
    const int u0   = ub * 32;
    const int b0   = bb * 32;
    const int half = tid >> 7;             // k-half
    const int htid = tid & 127;
    const int ug   = htid & 7;             // 4-unit group
    const int bp   = htid >> 3;            // batch pair 0..15
    const int kbase = half * HALFK;
    // staging mapping (within half)
    const int srow = htid & 31;            // batch row
    const int skq  = (htid >> 5) * 16;     // k offset within chunk (16 floats)

    float* mysS = sS + half * (2 * DUPSZ);

    // W slice (reused 256 steps): 256 threads.
    {
        const int q  = (tid & 7) * 4;
        for (int k = tid >> 3; k < UNITS; k += 32) {
            *(float4*)(Ws + k * 32 + q) =
                *(const float4*)(W + (size_t)k * UNITS + u0 + q);
        }
    }

    // Init state buffer 0 with x0 (this block's tile): half-0 threads.
    if (tid < 128) {
        float4 xv = *(const float4*)(x0 + u0 + ug * 4);
        int gb = b0 + bp * 2;
        *(float4*)(&g_S[0][(size_t)gb * UNITS + u0 + ug * 4])       = xv;
        *(float4*)(&g_S[0][(size_t)(gb + 1) * UNITS + u0 + ug * 4]) = xv;
    }

    unsigned gen = *(volatile unsigned*)&g_gen[bb];
    group_barrier(bb, gen);

    float es[8];
    #pragma unroll
    for (int i = 0; i < 8; i++) es[i] = 0.0f;

    int cur = 0;
    float4 pf[4];

    // Stage chunk 0 of step 0.
    {
        const float* src = g_S[cur] + (size_t)(b0 + srow) * UNITS + kbase + skq;
        #pragma unroll
        for (int q = 0; q < 4; q++) pf[q] = __ldcg((const float4*)src + q);
        #pragma unroll
        for (int q = 0; q < 4; q++) {
            const float* v = (const float*)&pf[q];
            #pragma unroll
            for (int j = 0; j < 4; j++)
                *(float2*)(mysS + (skq + q * 4 + j) * 64 + srow * 2)
                    = make_float2(v[j], v[j]);
        }
    }
    __syncthreads();

    const int gb = b0 + bp * 2;

    for (int t = 0; t < TIME; t++) {
        unsigned long long a0 = 0ULL, a1 = 0ULL, a2 = 0ULL, a3 = 0ULL;
        const float* Sc = g_S[cur];

        // Prefetch h_t for the epilogue (half-0 threads own the epilogue).
        float4 h0, h1;
        float* op0 = out + ((size_t)gb * TP1 + t) * UNITS + u0 + ug * 4;
        float* op1 = op0 + (size_t)TP1 * UNITS;
        if (tid < 128) {
            h0 = __ldg((const float4*)op0);
            h1 = __ldg((const float4*)op1);
        }

        for (int c = 0; c < NCH; c++) {
            if (c + 1 < NCH) {
                const float* src = Sc + (size_t)(b0 + srow) * UNITS
                                   + kbase + (c + 1) * CHUNKB + skq;
                #pragma unroll
                for (int q = 0; q < 4; q++) pf[q] = __ldcg((const float4*)src + q);
            }

            const float* wb = Ws + (kbase + c * CHUNKB) * 32 + ug * 4;
            const float* db = mysS + (c & 1) * DUPSZ + bp * 4;
            #pragma unroll 16
            for (int kk = 0; kk < CHUNKB; kk++) {
                ulonglong2 w = *(const ulonglong2*)(wb + kk * 32);
                ulonglong2 s = *(const ulonglong2*)(db + kk * 64);
                ffma2(a0, w.x, s.x);
                ffma2(a1, w.y, s.x);
                ffma2(a2, w.x, s.y);
                ffma2(a3, w.y, s.y);
            }

            if (c + 1 < NCH) {
                float* dst = mysS + ((c + 1) & 1) * DUPSZ;
                #pragma unroll
                for (int q = 0; q < 4; q++) {
                    const float* v = (const float*)&pf[q];
                    #pragma unroll
                    for (int j = 0; j < 4; j++)
                        *(float2*)(dst + (skq + q * 4 + j) * 64 + srow * 2)
                            = make_float2(v[j], v[j]);
                }
            }
            __syncthreads();
        }

        // Cross-half partial reduction through smem (buffers are free now).
        unsigned long long* sP = (unsigned long long*)sS;
        if (tid >= 128) {
            ulonglong2* p = (ulonglong2*)(sP + htid * 4);
            p[0] = make_ulonglong2(a0, a1);
            p[1] = make_ulonglong2(a2, a3);
        }
        __syncthreads();

        if (tid < 128) {
            ulonglong2 p0 = ((const ulonglong2*)(sP + htid * 4))[0];
            ulonglong2 p1 = ((const ulonglong2*)(sP + htid * 4))[1];
            fadd2(a0, p0.x); fadd2(a1, p0.y);
            fadd2(a2, p1.x); fadd2(a3, p1.y);

            float2 f0 = u2f2(a0), f1 = u2f2(a1), f2 = u2f2(a2), f3 = u2f2(a3);
            float4 s0, s1;
            s0.x = tanhf(h0.x + f0.x); s0.y = tanhf(h0.y + f0.y);
            s0.z = tanhf(h0.z + f1.x); s0.w = tanhf(h0.w + f1.y);
            s1.x = tanhf(h1.x + f2.x); s1.y = tanhf(h1.y + f2.y);
            s1.z = tanhf(h1.z + f3.x); s1.w = tanhf(h1.w + f3.y);
            *(float4*)op0 = s0;
            *(float4*)op1 = s1;

            float* n0 = &g_S[cur ^ 1][(size_t)gb * UNITS + u0 + ug * 4];
            *(float4*)n0           = s0;
            *(float4*)(n0 + UNITS) = s1;

            es[0] += __expf(s0.x); es[1] += __expf(s0.y);
            es[2] += __expf(s0.z); es[3] += __expf(s0.w);
            es[4] += __expf(s1.x); es[5] += __expf(s1.y);
            es[6] += __expf(s1.z); es[7] += __expf(s1.w);
        }

        cur ^= 1;
        if (t + 1 < TIME) {
            group_barrier(bb, gen);
            // Stage chunk 0 of the next step.
            const float* src = g_S[cur] + (size_t)(b0 + srow) * UNITS + kbase + skq;
            #pragma unroll
            for (int q = 0; q < 4; q++) pf[q] = __ldcg((const float4*)src + q);
            #pragma unroll
            for (int q = 0; q < 4; q++) {
                const float* v = (const float*)&pf[q];
                #pragma unroll
                for (int j = 0; j < 4; j++)
                    *(float2*)(mysS + (skq + q * 4 + j) * 64 + srow * 2)
                        = make_float2(v[j], v[j]);
            }
            __syncthreads();
        }
    }

    // Terminal row: log(tanh(mean_t exp(s))), beta = 1.  Half-0 threads.
    if (tid < 128) {
        const float inv = 1.0f / (float)TIME;
        float* op0 = out + ((size_t)gb * TP1 + TIME) * UNITS + u0 + ug * 4;
        float* op1 = op0 + (size_t)TP1 * UNITS;
        float4 t0, t1;
        t0.x = logf(tanhf(es[0] * inv)); t0.y = logf(tanhf(es[1] * inv));
        t0.z = logf(tanhf(es[2] * inv)); t0.w = logf(tanhf(es[3] * inv));
        t1.x = logf(tanhf(es[4] * inv)); t1.y = logf(tanhf(es[5] * inv));
        t1.z = logf(tanhf(es[6] * inv)); t1.w = logf(tanhf(es[7] * inv));
        *(float4*)op0 = t0;
        *(float4*)op1 = t1;
    }
}

// ---------------------------------------------------------------------------
// Launch
// ---------------------------------------------------------------------------
extern "C" void kernel_launch(void* const* d_in, const int* in_sizes, int n_in,
                              void* d_out, int out_size) {
    const float* X    = (const float*)d_in[0];  // [128,256,512]
    const float* R    = (const float*)d_in[1];  // [512,1024]
    const float* W    = (const float*)d_in[2];  // [1024,1024]
    const float* bias = (const float*)d_in[3];  // [1024]
    const float* x0   = (const float*)d_in[4];  // [1024]
    float* out = (float*)d_out;                 // [128,257,1024]

    (void)in_sizes; (void)n_in; (void)out_size;

    dim3 gridA(UNITS / 64, (BATCH * TIME) / 64);
    hin_gemm_kernel<<<gridA, 256>>>(X, R, bias, out);

    const int smemB = (UNITS * 32 + 4 * DUPSZ) * (int)sizeof(float);  // 196608 B
    cudaFuncSetAttribute(recurrent_kernel,
                         cudaFuncAttributeMaxDynamicSharedMemorySize, smemB);
    recurrent_kernel<<<NBLK, 256, smemB>>>(W, x0, out);
}

// round 6
// speedup vs baseline: 1.0701x; 1.0259x over previous
#include <cuda_runtime.h>

#define BATCH  128
#define TIME   256
#define FDIM   512
#define UNITS  1024
#define TP1    257

#define NBLK   128      // 4 batch-groups x 32 unit-tiles
#define KG     16       // k-groups per block
#define KWIN   64       // k per group
#define SUBK   8        // k per staged sub-chunk
#define NSUB   (KWIN / SUBK)            // 8
#define STGF   (KG * SUBK * 64)         // floats per stage buffer = 8192

// ---------------------------------------------------------------------------
// Scratch: transposed+duplicated state  g_Sd[buf][unit k][2*batch], 2 MB.
// ---------------------------------------------------------------------------
__device__ float    g_Sd[2][UNITS][2 * BATCH];
__device__ unsigned g_cnt[4];
__device__ unsigned g_gen[4];

// ---------------------------------------------------------------------------
// Packed fp32x2 ops (ptxas won't emit these from C++).
// ---------------------------------------------------------------------------
__device__ __forceinline__ void ffma2(unsigned long long& d,
                                      unsigned long long a,
                                      unsigned long long b) {
    asm("fma.rn.f32x2 %0, %1, %2, %0;" : "+l"(d) : "l"(a), "l"(b));
}
__device__ __forceinline__ void fadd2(unsigned long long& d,
                                      unsigned long long a) {
    asm("add.rn.f32x2 %0, %0, %1;" : "+l"(d) : "l"(a));
}
__device__ __forceinline__ float2 u2f2(unsigned long long v) {
    float2 f;
    f.x = __uint_as_float((unsigned)(v & 0xffffffffu));
    f.y = __uint_as_float((unsigned)(v >> 32));
    return f;
}

// ---------------------------------------------------------------------------
// Barrier among the 32 blocks of one batch group.
// ---------------------------------------------------------------------------
__device__ __forceinline__ void group_barrier(int g, unsigned& gen) {
    __syncthreads();
    if (threadIdx.x == 0) {
        __threadfence();
        unsigned old = atomicAdd(&g_cnt[g], 1u);
        if (old == 31u) {
            g_cnt[g] = 0u;
            __threadfence();
            atomicAdd(&g_gen[g], 1u);
        } else {
            while (*(volatile unsigned*)&g_gen[g] == gen) { __nanosleep(20); }
        }
        __threadfence();
    }
    __syncthreads();
    gen += 1u;
}

// ---------------------------------------------------------------------------
// Kernel A: h = inputs @ R + bias -> out[b, t, :].  (unchanged from R5)
// ---------------------------------------------------------------------------
#define ASTRIDE 132

__global__ void __launch_bounds__(256) hin_gemm_kernel(
    const float* __restrict__ X,
    const float* __restrict__ R,
    const float* __restrict__ bias,
    float* __restrict__ out)
{
    __shared__ float Asd[16 * ASTRIDE];
    __shared__ float Bs[16 * 64];

    const int tid  = threadIdx.x;
    const int tx   = tid & 15;
    const int ty   = tid >> 4;
    const int row0 = blockIdx.y * 64;
    const int col0 = blockIdx.x * 64;

    const int li = tid >> 2;
    const int lj = (tid & 3) * 4;
    const int rj = tid >> 4;
    const int ri = (tid & 15) * 4;

    unsigned long long cc[4][2];
    #pragma unroll
    for (int i = 0; i < 4; i++) { cc[i][0] = 0ULL; cc[i][1] = 0ULL; }

    float4 a = *(const float4*)(X + (size_t)(row0 + li) * FDIM + lj);
    float4 b = *(const float4*)(R + (size_t)rj * UNITS + col0 + ri);

    for (int k0 = 0; k0 < FDIM; k0 += 16) {
        *(float2*)(Asd + (lj + 0) * ASTRIDE + li * 2) = make_float2(a.x, a.x);
        *(float2*)(Asd + (lj + 1) * ASTRIDE + li * 2) = make_float2(a.y, a.y);
        *(float2*)(Asd + (lj + 2) * ASTRIDE + li * 2) = make_float2(a.z, a.z);
        *(float2*)(Asd + (lj + 3) * ASTRIDE + li * 2) = make_float2(a.w, a.w);
        *(float4*)(Bs + rj * 64 + ri) = b;
        __syncthreads();

        if (k0 + 16 < FDIM) {
            a = *(const float4*)(X + (size_t)(row0 + li) * FDIM + k0 + 16 + lj);
            b = *(const float4*)(R + (size_t)(k0 + 16 + rj) * UNITS + col0 + ri);
        }

        #pragma unroll
        for (int k = 0; k < 16; k++) {
            ulonglong2 a01 = *(const ulonglong2*)(Asd + k * ASTRIDE + ty * 8);
            ulonglong2 a23 = *(const ulonglong2*)(Asd + k * ASTRIDE + ty * 8 + 4);
            ulonglong2 bv  = *(const ulonglong2*)(Bs + k * 64 + tx * 4);
            ffma2(cc[0][0], a01.x, bv.x); ffma2(cc[0][1], a01.x, bv.y);
            ffma2(cc[1][0], a01.y, bv.x); ffma2(cc[1][1], a01.y, bv.y);
            ffma2(cc[2][0], a23.x, bv.x); ffma2(cc[2][1], a23.x, bv.y);
            ffma2(cc[3][0], a23.y, bv.x); ffma2(cc[3][1], a23.y, bv.y);
        }
        __syncthreads();
    }

    float4 bv = *(const float4*)(bias + col0 + tx * 4);
    #pragma unroll
    for (int i = 0; i < 4; i++) {
        int m    = row0 + ty * 4 + i;
        int bidx = m >> 8;
        int tt   = m & 255;
        float2 lo = u2f2(cc[i][0]);
        float2 hi = u2f2(cc[i][1]);
        float4 v;
        v.x = lo.x + bv.x; v.y = lo.y + bv.y;
        v.z = hi.x + bv.z; v.w = hi.y + bv.w;
        *(float4*)(out + ((size_t)(bidx * TP1 + tt)) * UNITS + col0 + tx * 4) = v;
    }
}

// ---------------------------------------------------------------------------
// Kernel B: persistent recurrence.
//   Block (bb, ub): batches [bb*32,+32), units [ub*32,+32).
//   16 k-groups x 16 threads; thread tile 8 units (4 pairs) x 8 batches;
//   all-FFMA2; W (128 KB) resident in smem; state staged from g_Sd with
//   XOR bank swizzle; cross-group reduction via smem partials.
// ---------------------------------------------------------------------------
__global__ void __launch_bounds__(256) recurrent_kernel(
    const float* __restrict__ W,
    const float* __restrict__ x0,
    float* __restrict__ out)
{
    extern __shared__ float sm[];
    float* Ws    = sm;                 // [1024][32]  = 32768 floats
    char*  stage = (char*)(sm + 32768); // 2 bufs x 32768 B (also sP region)

    const int tid = threadIdx.x;
    const int ub  = blockIdx.x & 31;
    const int bb  = blockIdx.x >> 5;
    const int u0  = ub * 32;
    const int b0  = bb * 32;

    const int kg  = tid >> 4;          // k-group 0..15
    const int l16 = tid & 15;
    const int ugi = l16 & 3;           // unit quad (8 units = 4 pairs)
    const int bgi = l16 >> 2;          // batch octet (8 batches)

    // staging role: 16 threads stage 8 rows x 64 floats (dup) per sub-chunk
    const int srow = l16 >> 1;         // k row within sub-chunk (0..7)
    const int shalf = l16 & 1;         // which 32-float half of the row
    const int r16 = srow * 16;         // byte swizzle key

    // epilogue mapping: thread -> (batch eb, unit-pairs epu0, epu0+1)
    const int eb   = tid >> 3;         // 0..31
    const int epu0 = (tid & 7) * 2;    // 0,2,..,14

    // Fill W slice [1024][32] (native unit pairs), reused 256 steps.
    {
        const int q = (tid & 7) * 4;
        for (int k = tid >> 3; k < UNITS; k += 32)
            *(float4*)(Ws + k * 32 + q) =
                *(const float4*)(W + (size_t)k * UNITS + u0 + q);
    }

    // Init duplicated state with x0: one block per batch group does it.
    if (ub == 0) {
        #pragma unroll
        for (int rr = 0; rr < 4; rr++) {
            int k = tid * 4 + rr;
            float v = x0[k];
            float2 d = make_float2(v, v);
            float2* row = (float2*)&g_Sd[0][k][2 * b0];
            #pragma unroll
            for (int b = 0; b < 32; b++) row[b] = d;
        }
    }

    unsigned gen = *(volatile unsigned*)&g_gen[bb];
    group_barrier(bb, gen);

    // Per-thread precomputed swizzled s-load byte offsets (within kg block):
    // logical float col L = bgi*16 + q*4 ->  half(L)*128 + q4(L)*16 bytes
    unsigned soff[4];
    #pragma unroll
    for (int q = 0; q < 4; q++) {
        int L = bgi * 16 + q * 4;
        soff[q] = (unsigned)((L >> 5) * 128 + ((L >> 2) & 7) * 16);
    }

    float es[4] = {0.f, 0.f, 0.f, 0.f};
    int cur = 0;
    float4 pf[8];

    // Stage chunk 0 of step 0: rows k = kg*64 + srow, logical cols half*32+..
    {
        const float* gr = &g_Sd[cur][kg * KWIN + srow][2 * b0 + shalf * 32];
        #pragma unroll
        for (int q4 = 0; q4 < 8; q4++)
            pf[q4] = __ldcg((const float4*)(gr + q4 * 4));
        char* db = stage + kg * 2048 + srow * 256 + shalf * 128;
        #pragma unroll
        for (int q4 = 0; q4 < 8; q4++)
            *(float4*)(db + ((q4 * 16) ^ r16)) = pf[q4];
    }
    __syncthreads();

    const size_t outrow = ((size_t)(b0 + eb) * TP1) * UNITS + u0 + epu0 * 2;

    for (int t = 0; t < TIME; t++) {
        // h_t prefetch for epilogue (row t never written by us before now)
        float4 h = __ldg((const float4*)(out + outrow + (size_t)t * UNITS));

        unsigned long long acc[32];
        #pragma unroll
        for (int i = 0; i < 32; i++) acc[i] = 0ULL;

        const char* wb = (const char*)Ws + (size_t)(kg * KWIN) * 128 + ugi * 32;

        for (int c = 0; c < NSUB; c++) {
            if (c + 1 < NSUB) {
                const float* gr = &g_Sd[cur][kg * KWIN + (c + 1) * SUBK + srow]
                                         [2 * b0 + shalf * 32];
                #pragma unroll
                for (int q4 = 0; q4 < 8; q4++)
                    pf[q4] = __ldcg((const float4*)(gr + q4 * 4));
            }

            const char* wc = wb + (size_t)c * SUBK * 128;
            const char* sb = stage + (c & 1) * 32768 + kg * 2048;
            #pragma unroll
            for (int kl = 0; kl < SUBK; kl++) {
                ulonglong2 w01 = *(const ulonglong2*)(wc + kl * 128);
                ulonglong2 w23 = *(const ulonglong2*)(wc + kl * 128 + 16);
                unsigned long long wv0 = w01.x, wv1 = w01.y;
                unsigned long long wv2 = w23.x, wv3 = w23.y;
                unsigned long long sv[8];
                #pragma unroll
                for (int q = 0; q < 4; q++) {
                    ulonglong2 sq = *(const ulonglong2*)
                        (sb + (soff[q] ^ (unsigned)(kl * 16)) + kl * 256);
                    sv[2 * q]     = sq.x;
                    sv[2 * q + 1] = sq.y;
                }
                #pragma unroll
                for (int j = 0; j < 8; j++) {
                    ffma2(acc[0 * 8 + j], wv0, sv[j]);
                    ffma2(acc[1 * 8 + j], wv1, sv[j]);
                    ffma2(acc[2 * 8 + j], wv2, sv[j]);
                    ffma2(acc[3 * 8 + j], wv3, sv[j]);
                }
            }

            if (c + 1 < NSUB) {
                char* db = stage + ((c + 1) & 1) * 32768
                           + kg * 2048 + srow * 256 + shalf * 128;
                #pragma unroll
                for (int q4 = 0; q4 < 8; q4++)
                    *(float4*)(db + ((q4 * 16) ^ r16)) = pf[q4];
            }
            __syncthreads();
        }

        // Store partials (lane-swizzled, 4-way max):
        unsigned long long* sP = (unsigned long long*)stage;
        {
            const int lane = tid & 31;
            #pragma unroll
            for (int i = 0; i < 16; i++) {
                int slot = (i + lane) & 15;
                *(ulonglong2*)(sP + tid * 32 + slot * 2) =
                    make_ulonglong2(acc[2 * i], acc[2 * i + 1]);
            }
        }
        __syncthreads();

        // Reduce 16 k-group partials; epilogue across all 256 threads.
        {
            const int bgi_e = eb >> 3;
            const int j_e   = eb & 7;
            unsigned long long red[2];
            #pragma unroll
            for (int pp = 0; pp < 2; pp++) {
                int pu  = epu0 + pp;
                int p   = pu & 3;
                int ug  = pu >> 2;
                int a   = p * 8 + j_e;
                int i   = a >> 1;
                int par = a & 1;
                unsigned long long sum = 0ULL;
                #pragma unroll
                for (int g = 0; g < KG; g++) {
                    int tau  = g * 16 + bgi_e * 4 + ug;
                    int slot = (i + (tau & 31)) & 15;
                    fadd2(sum, sP[tau * 32 + slot * 2 + par]);
                }
                red[pp] = sum;
            }

            float2 fa = u2f2(red[0]);
            float2 fb = u2f2(red[1]);
            float4 s;
            s.x = tanhf(h.x + fa.x);
            s.y = tanhf(h.y + fa.y);
            s.z = tanhf(h.z + fb.x);
            s.w = tanhf(h.w + fb.y);
            *(float4*)(out + outrow + (size_t)t * UNITS) = s;

            // next state (transposed + duplicated)
            const int col = 2 * (b0 + eb);
            const int ku  = u0 + epu0 * 2;
            const int nxt = cur ^ 1;
            *(float2*)&g_Sd[nxt][ku + 0][col] = make_float2(s.x, s.x);
            *(float2*)&g_Sd[nxt][ku + 1][col] = make_float2(s.y, s.y);
            *(float2*)&g_Sd[nxt][ku + 2][col] = make_float2(s.z, s.z);
            *(float2*)&g_Sd[nxt][ku + 3][col] = make_float2(s.w, s.w);

            es[0] += __expf(s.x);
            es[1] += __expf(s.y);
            es[2] += __expf(s.z);
            es[3] += __expf(s.w);
        }

        cur ^= 1;
        if (t + 1 < TIME) {
            group_barrier(bb, gen);
            const float* gr = &g_Sd[cur][kg * KWIN + srow][2 * b0 + shalf * 32];
            #pragma unroll
            for (int q4 = 0; q4 < 8; q4++)
                pf[q4] = __ldcg((const float4*)(gr + q4 * 4));
            char* db = stage + kg * 2048 + srow * 256 + shalf * 128;
            #pragma unroll
            for (int q4 = 0; q4 < 8; q4++)
                *(float4*)(db + ((q4 * 16) ^ r16)) = pf[q4];
            __syncthreads();
        }
    }

    // Terminal row: log(tanh(mean_t exp(s))), beta = 1.
    {
        const float inv = 1.0f / (float)TIME;
        float4 tm;
        tm.x = logf(tanhf(es[0] * inv));
        tm.y = logf(tanhf(es[1] * inv));
        tm.z = logf(tanhf(es[2] * inv));
        tm.w = logf(tanhf(es[3] * inv));
        *(float4*)(out + outrow + (size_t)TIME * UNITS) = tm;
    }
}

// ---------------------------------------------------------------------------
// Launch
// ---------------------------------------------------------------------------
extern "C" void kernel_launch(void* const* d_in, const int* in_sizes, int n_in,
                              void* d_out, int out_size) {
    const float* X    = (const float*)d_in[0];  // [128,256,512]
    const float* R    = (const float*)d_in[1];  // [512,1024]
    const float* W    = (const float*)d_in[2];  // [1024,1024]
    const float* bias = (const float*)d_in[3];  // [1024]
    const float* x0   = (const float*)d_in[4];  // [1024]
    float* out = (float*)d_out;                 // [128,257,1024]

    (void)in_sizes; (void)n_in; (void)out_size;

    dim3 gridA(UNITS / 64, (BATCH * TIME) / 64);
    hin_gemm_kernel<<<gridA, 256>>>(X, R, bias, out);

    const int smemB = 32768 * 4 + 2 * 32768;   // 131072 + 65536 = 196608 B
    cudaFuncSetAttribute(recurrent_kernel,
                         cudaFuncAttributeMaxDynamicSharedMemorySize, smemB);
    recurrent_kernel<<<NBLK, 256, smemB>>>(W, x0, out);
}

// round 9
// speedup vs baseline: 1.3380x; 1.2503x over previous
#include <cuda_runtime.h>
#include <cuda_fp16.h>

#define BATCH  128
#define TIME   256
#define FDIM   512
#define UNITS  1024
#define TP1    257
#define NCTA   64

// ---- recurrent kernel smem layout (bytes) ----
#define WT_STRIDE 2064                       // 1024 fp16 + 16B pad -> conflict-free ldmatrix
#define SM_WTH    0
#define SM_WTL    (16 * WT_STRIDE)           // 33024
#define SM_AB     (2 * 16 * WT_STRIDE)       // 66048
#define AB_SZ     (128 * 80)                 // 10240 (128 rows x 32k fp16, 80B stride)
#define SM_PART   (SM_AB + 8 * AB_SZ)        // 147968
#define SM_TOTAL  (SM_PART + 2 * 128 * 64)   // 164352

// ---------------------------------------------------------------------------
// Scratch: DOUBLE-BUFFERED fp16 hi/lo state + barrier counters.
// ---------------------------------------------------------------------------
__device__ __align__(256) __half g_SH[2][BATCH * UNITS];
__device__ __align__(256) __half g_SL[2][BATCH * UNITS];
__device__ unsigned g_cnt[8];
__device__ unsigned g_cnt2;
__device__ unsigned g_gen;

// ---------------------------------------------------------------------------
// PTX helpers (all baseline ISA, sm_80-generic: compile under compute_103)
// ---------------------------------------------------------------------------
__device__ __forceinline__ unsigned smem_u32(const void* p) {
    unsigned a;
    asm("{ .reg .u64 t; cvta.to.shared.u64 t, %1; cvt.u32.u64 %0, t; }"
        : "=r"(a) : "l"(p));
    return a;
}
__device__ __forceinline__ void ldm4(unsigned a, unsigned r[4]) {
    asm volatile("ldmatrix.sync.aligned.m8n8.x4.shared.b16 {%0,%1,%2,%3}, [%4];"
                 : "=r"(r[0]), "=r"(r[1]), "=r"(r[2]), "=r"(r[3]) : "r"(a));
}
__device__ __forceinline__ void mma_f16(float c[4], const unsigned a[4],
                                        unsigned b0, unsigned b1) {
    asm volatile(
        "mma.sync.aligned.m16n8k16.row.col.f32.f16.f16.f32 "
        "{%0,%1,%2,%3}, {%4,%5,%6,%7}, {%8,%9}, {%0,%1,%2,%3};"
        : "+f"(c[0]), "+f"(c[1]), "+f"(c[2]), "+f"(c[3])
        : "r"(a[0]), "r"(a[1]), "r"(a[2]), "r"(a[3]), "r"(b0), "r"(b1));
}
__device__ __forceinline__ void cp16(unsigned dst, const void* src) {
    asm volatile("cp.async.cg.shared.global [%0], [%1], 16;"
                 :: "r"(dst), "l"(src) : "memory");
}
__device__ __forceinline__ void cp_commit() {
    asm volatile("cp.async.commit_group;" ::: "memory");
}
__device__ __forceinline__ void cp_wait1() {
    asm volatile("cp.async.wait_group 1;" ::: "memory");
}
__device__ __forceinline__ void cp_wait0() {
    asm volatile("cp.async.wait_group 0;" ::: "memory");
}
// Packed fp32x2 FMA (kernel A)
__device__ __forceinline__ void ffma2(unsigned long long& d,
                                      unsigned long long a,
                                      unsigned long long b) {
    asm("fma.rn.f32x2 %0, %1, %2, %0;" : "+l"(d) : "l"(a), "l"(b));
}
__device__ __forceinline__ float2 u2f2(unsigned long long v) {
    float2 f;
    f.x = __uint_as_float((unsigned)(v & 0xffffffffu));
    f.y = __uint_as_float((unsigned)(v >> 32));
    return f;
}

// ---------------------------------------------------------------------------
// Hierarchical grid barrier over 64 CTAs (8 groups of 8).
// ---------------------------------------------------------------------------
__device__ __forceinline__ void gbar(unsigned& gen) {
    __syncthreads();
    if (threadIdx.x == 0) {
        __threadfence();
        int g = blockIdx.x >> 3;
        if (atomicAdd(&g_cnt[g], 1u) == 7u) {
            g_cnt[g] = 0u;
            __threadfence();
            if (atomicAdd(&g_cnt2, 1u) == 7u) {
                g_cnt2 = 0u;
                __threadfence();
                atomicAdd(&g_gen, 1u);
            }
        }
        while (*(volatile unsigned*)&g_gen == gen) { __nanosleep(20); }
        __threadfence();
    }
    __syncthreads();
    gen += 1u;
}

// ---------------------------------------------------------------------------
// Kernel A: h = inputs @ R + bias -> out[b, t, :]   (unchanged, passing)
// ---------------------------------------------------------------------------
#define ASTRIDE 132

__global__ void __launch_bounds__(256) hin_gemm_kernel(
    const float* __restrict__ X,
    const float* __restrict__ R,
    const float* __restrict__ bias,
    float* __restrict__ out)
{
    __shared__ float Asd[16 * ASTRIDE];
    __shared__ float Bs[16 * 64];

    const int tid  = threadIdx.x;
    const int tx   = tid & 15;
    const int ty   = tid >> 4;
    const int row0 = blockIdx.y * 64;
    const int col0 = blockIdx.x * 64;

    const int li = tid >> 2;
    const int lj = (tid & 3) * 4;
    const int rj = tid >> 4;
    const int ri = (tid & 15) * 4;

    unsigned long long cc[4][2];
    #pragma unroll
    for (int i = 0; i < 4; i++) { cc[i][0] = 0ULL; cc[i][1] = 0ULL; }

    float4 a = *(const float4*)(X + (size_t)(row0 + li) * FDIM + lj);
    float4 b = *(const float4*)(R + (size_t)rj * UNITS + col0 + ri);

    for (int k0 = 0; k0 < FDIM; k0 += 16) {
        *(float2*)(Asd + (lj + 0) * ASTRIDE + li * 2) = make_float2(a.x, a.x);
        *(float2*)(Asd + (lj + 1) * ASTRIDE + li * 2) = make_float2(a.y, a.y);
        *(float2*)(Asd + (lj + 2) * ASTRIDE + li * 2) = make_float2(a.z, a.z);
        *(float2*)(Asd + (lj + 3) * ASTRIDE + li * 2) = make_float2(a.w, a.w);
        *(float4*)(Bs + rj * 64 + ri) = b;
        __syncthreads();

        if (k0 + 16 < FDIM) {
            a = *(const float4*)(X + (size_t)(row0 + li) * FDIM + k0 + 16 + lj);
            b = *(const float4*)(R + (size_t)(k0 + 16 + rj) * UNITS + col0 + ri);
        }

        #pragma unroll
        for (int k = 0; k < 16; k++) {
            ulonglong2 a01 = *(const ulonglong2*)(Asd + k * ASTRIDE + ty * 8);
            ulonglong2 a23 = *(const ulonglong2*)(Asd + k * ASTRIDE + ty * 8 + 4);
            ulonglong2 bv  = *(const ulonglong2*)(Bs + k * 64 + tx * 4);
            ffma2(cc[0][0], a01.x, bv.x); ffma2(cc[0][1], a01.x, bv.y);
            ffma2(cc[1][0], a01.y, bv.x); ffma2(cc[1][1], a01.y, bv.y);
            ffma2(cc[2][0], a23.x, bv.x); ffma2(cc[2][1], a23.x, bv.y);
            ffma2(cc[3][0], a23.y, bv.x); ffma2(cc[3][1], a23.y, bv.y);
        }
        __syncthreads();
    }

    float4 bv = *(const float4*)(bias + col0 + tx * 4);
    #pragma unroll
    for (int i = 0; i < 4; i++) {
        int m    = row0 + ty * 4 + i;
        int bidx = m >> 8;
        int tt   = m & 255;
        float2 lo = u2f2(cc[i][0]);
        float2 hi = u2f2(cc[i][1]);
        float4 v;
        v.x = lo.x + bv.x; v.y = lo.y + bv.y;
        v.z = hi.x + bv.z; v.w = hi.y + bv.w;
        *(float4*)(out + ((size_t)(bidx * TP1 + tt)) * UNITS + col0 + tx * 4) = v;
    }
}

// ---------------------------------------------------------------------------
// Kernel B: persistent HMMA recurrence. 64 CTAs x 256 threads.
//   CTA: units [u0, u0+16), all 128 batches. W slice (fp16 hi/lo) resident in
//   SMEM. 8 warps: (wid&3)=32-row batch tile, (wid>>2)=K half. Warp tile
//   m32 x n16, mma.sync m16n8k16 fp16, fp32 accum, 3-product hi/lo split.
// ---------------------------------------------------------------------------
__global__ void __launch_bounds__(256) recurrent_kernel(
    const float* __restrict__ W,
    const float* __restrict__ x0,
    float* __restrict__ out)
{
    extern __shared__ __align__(128) char smem[];
    const unsigned sb = smem_u32(smem);
    const int tid = threadIdx.x;
    const int wid = tid >> 5;
    const int lid = tid & 31;
    const int u0  = blockIdx.x * 16;

    // --- Convert W slice -> SMEM fp16 hi/lo, Wt[n][k] layout, padded rows.
    for (int idx = tid; idx < 16 * UNITS; idx += 256) {
        int n = idx & 15;
        int k = idx >> 4;
        float v = __ldg(W + (size_t)k * UNITS + u0 + n);
        __half hi = __float2half_rn(v);
        __half lo = __float2half_rn(v - __half2float(hi));
        *(__half*)(smem + SM_WTH + n * WT_STRIDE + k * 2) = hi;
        *(__half*)(smem + SM_WTL + n * WT_STRIDE + k * 2) = lo;
    }

    // --- Init state buffer 0 with x0 for this CTA's unit columns.
    {
        int er = tid >> 1;
        int ec = (tid & 1) * 8;
        #pragma unroll
        for (int j = 0; j < 8; j++) {
            float v = x0[u0 + ec + j];
            __half hi = __float2half_rn(v);
            __half lo = __float2half_rn(v - __half2float(hi));
            g_SH[0][(size_t)er * UNITS + u0 + ec + j] = hi;
            g_SL[0][(size_t)er * UNITS + u0 + ec + j] = lo;
        }
    }
    __threadfence();

    unsigned gen = *(volatile unsigned*)&g_gen;
    gbar(gen);

    // --- Per-thread staging precompute. tau = (khalf, hi/lo) target.
    const int tau   = tid >> 6;          // 0..3
    const int khs   = tau >> 1;
    const int part  = tau & 1;
    const int rem   = tid & 63;
    const int prow  = rem >> 2;          // 0..15 base row
    const int ppos  = rem & 3;           // 16B chunk in row
    const size_t srcRel = (size_t)prow * 2048 + (size_t)khs * 1024 + ppos * 16;
    const unsigned dstRel0 = (unsigned)(SM_AB + (khs * 4 + part) * AB_SZ
                                        + prow * 80 + ppos * 16);

    // --- Per-warp MMA precompute.
    const int kh = wid >> 2;             // K half
    const int rb = (wid & 3) * 32;       // batch row base
    const unsigned aoff0 = (unsigned)((rb + (lid & 15)) * 80 + (lid >> 4) * 16);
    const int b_n    = (lid & 7) | ((lid >> 1) & 8);
    const int b_koff = ((lid >> 3) & 1) * 16;        // bytes
    const unsigned bofl = (unsigned)(b_n * WT_STRIDE + b_koff);

    // --- Epilogue mapping.
    const int er = tid >> 1;
    const int ec = (tid & 1) * 8;
    const size_t outbase = ((size_t)er * TP1) * UNITS + u0 + ec;

    float es[8];
    #pragma unroll
    for (int i = 0; i < 8; i++) es[i] = 0.0f;

    int cur = 0;

    for (int t = 0; t < TIME; t++) {
        const char* srcBase =
            (const char*)(part ? g_SL[cur] : g_SH[cur]) + srcRel;

        float acc[2][2][4];
        #pragma unroll
        for (int mi = 0; mi < 2; mi++)
            #pragma unroll
            for (int ni = 0; ni < 2; ni++)
                #pragma unroll
                for (int q = 0; q < 4; q++) acc[mi][ni][q] = 0.0f;

        // stage chunk 0
        {
            unsigned d0 = sb + dstRel0;
            #pragma unroll
            for (int j = 0; j < 8; j++)
                cp16(d0 + j * 1280u, srcBase + (size_t)j * 32768);
            cp_commit();
        }

        for (int c = 0; c < 16; c++) {
            if (c < 15) {
                const char* s1 = srcBase + (c + 1) * 64;
                unsigned d1 = sb + dstRel0 + (unsigned)(((c + 1) & 1) * 2 * AB_SZ);
                #pragma unroll
                for (int j = 0; j < 8; j++)
                    cp16(d1 + j * 1280u, s1 + (size_t)j * 32768);
                cp_commit();
                cp_wait1();
            } else {
                cp_wait0();
            }
            __syncthreads();

            // buffer index = kh*4 + part + db*2  (FIX: AL = AH + AB_SZ)
            const unsigned AH = sb + (unsigned)(SM_AB + (kh * 4 + (c & 1) * 2) * AB_SZ);
            const unsigned AL = AH + (unsigned)AB_SZ;
            #pragma unroll
            for (int g = 0; g < 2; g++) {
                unsigned ah0[4], ah1[4], al0[4], al1[4], bh[4], bl[4];
                unsigned ab = AH + aoff0 + g * 32u;
                ldm4(ab, ah0);
                ldm4(ab + 1280u, ah1);
                unsigned lb = AL + aoff0 + g * 32u;
                ldm4(lb, al0);
                ldm4(lb + 1280u, al1);
                unsigned kb2 = (unsigned)((kh * 512 + c * 32 + g * 16) * 2);
                ldm4(sb + SM_WTH + bofl + kb2, bh);
                ldm4(sb + SM_WTL + bofl + kb2, bl);

                mma_f16(acc[0][0], ah0, bh[0], bh[1]);
                mma_f16(acc[0][1], ah0, bh[2], bh[3]);
                mma_f16(acc[1][0], ah1, bh[0], bh[1]);
                mma_f16(acc[1][1], ah1, bh[2], bh[3]);
                mma_f16(acc[0][0], ah0, bl[0], bl[1]);
                mma_f16(acc[0][1], ah0, bl[2], bl[3]);
                mma_f16(acc[1][0], ah1, bl[0], bl[1]);
                mma_f16(acc[1][1], ah1, bl[2], bl[3]);
                mma_f16(acc[0][0], al0, bh[0], bh[1]);
                mma_f16(acc[0][1], al0, bh[2], bh[3]);
                mma_f16(acc[1][0], al1, bh[0], bh[1]);
                mma_f16(acc[1][1], al1, bh[2], bh[3]);
            }
            __syncthreads();
        }

        // --- store K-half partials
        {
            float* P = (float*)(smem + SM_PART + kh * 8192);
            int pr = rb + (lid >> 2);
            int pc = (lid & 3) * 2;
            #pragma unroll
            for (int mi = 0; mi < 2; mi++)
                #pragma unroll
                for (int ni = 0; ni < 2; ni++) {
                    int base = (pr + mi * 16) * 16 + ni * 8 + pc;
                    *(float2*)(P + base) =
                        make_float2(acc[mi][ni][0], acc[mi][ni][1]);
                    *(float2*)(P + base + 128) =
                        make_float2(acc[mi][ni][2], acc[mi][ni][3]);
                }
        }
        __syncthreads();

        // --- epilogue: reduce halves, tanh, exp-acc, write out + next state
        {
            const float* P0 = (const float*)(smem + SM_PART) + er * 16 + ec;
            const float* P1 = P0 + 2048;
            float4 pa0 = *(const float4*)P0;
            float4 pa1 = *(const float4*)(P0 + 4);
            float4 pb0 = *(const float4*)P1;
            float4 pb1 = *(const float4*)(P1 + 4);

            float* orow = out + outbase + (size_t)t * UNITS;
            float4 h0 = *(const float4*)orow;
            float4 h1 = *(const float4*)(orow + 4);

            float s[8];
            s[0] = tanhf(h0.x + pa0.x + pb0.x);
            s[1] = tanhf(h0.y + pa0.y + pb0.y);
            s[2] = tanhf(h0.z + pa0.z + pb0.z);
            s[3] = tanhf(h0.w + pa0.w + pb0.w);
            s[4] = tanhf(h1.x + pa1.x + pb1.x);
            s[5] = tanhf(h1.y + pa1.y + pb1.y);
            s[6] = tanhf(h1.z + pa1.z + pb1.z);
            s[7] = tanhf(h1.w + pa1.w + pb1.w);

            *(float4*)orow       = make_float4(s[0], s[1], s[2], s[3]);
            *(float4*)(orow + 4) = make_float4(s[4], s[5], s[6], s[7]);

            const int nxt = cur ^ 1;
            unsigned pkH[4], pkL[4];
            #pragma unroll
            for (int j = 0; j < 4; j++) {
                float v0 = s[2 * j], v1 = s[2 * j + 1];
                __half h0v = __float2half_rn(v0);
                __half h1v = __float2half_rn(v1);
                __half l0v = __float2half_rn(v0 - __half2float(h0v));
                __half l1v = __float2half_rn(v1 - __half2float(h1v));
                pkH[j] = (unsigned)__half_as_ushort(h0v)
                       | ((unsigned)__half_as_ushort(h1v) << 16);
                pkL[j] = (unsigned)__half_as_ushort(l0v)
                       | ((unsigned)__half_as_ushort(l1v) << 16);
                es[2 * j]     += __expf(v0);
                es[2 * j + 1] += __expf(v1);
            }
            size_t soff = (size_t)er * UNITS + u0 + ec;
            *(uint4*)(g_SH[nxt] + soff) = make_uint4(pkH[0], pkH[1], pkH[2], pkH[3]);
            *(uint4*)(g_SL[nxt] + soff) = make_uint4(pkL[0], pkL[1], pkL[2], pkL[3]);
        }

        cur ^= 1;
        if (t + 1 < TIME) gbar(gen);
    }

    // --- terminal row: (1/beta) log(tanh(mean_t exp(beta*s))), beta=1
    {
        const float inv = 1.0f / (float)TIME;
        float* orow = out + outbase + (size_t)TIME * UNITS;
        float4 t0, t1;
        t0.x = logf(tanhf(es[0] * inv)); t0.y = logf(tanhf(es[1] * inv));
        t0.z = logf(tanhf(es[2] * inv)); t0.w = logf(tanhf(es[3] * inv));
        t1.x = logf(tanhf(es[4] * inv)); t1.y = logf(tanhf(es[5] * inv));
        t1.z = logf(tanhf(es[6] * inv)); t1.w = logf(tanhf(es[7] * inv));
        *(float4*)orow       = t0;
        *(float4*)(orow + 4) = t1;
    }
}

// ---------------------------------------------------------------------------
// Launch
// ---------------------------------------------------------------------------
extern "C" void kernel_launch(void* const* d_in, const int* in_sizes, int n_in,
                              void* d_out, int out_size) {
    const float* X    = (const float*)d_in[0];  // [128,256,512]
    const float* R    = (const float*)d_in[1];  // [512,1024]
    const float* W    = (const float*)d_in[2];  // [1024,1024]
    const float* bias = (const float*)d_in[3];  // [1024]
    const float* x0   = (const float*)d_in[4];  // [1024]
    float* out = (float*)d_out;                 // [128,257,1024]

    (void)in_sizes; (void)n_in; (void)out_size;

    dim3 gridA(UNITS / 64, (BATCH * TIME) / 64);
    hin_gemm_kernel<<<gridA, 256>>>(X, R, bias, out);

    cudaFuncSetAttribute(recurrent_kernel,
                         cudaFuncAttributeMaxDynamicSharedMemorySize, SM_TOTAL);
    recurrent_kernel<<<NCTA, 256, SM_TOTAL>>>(W, x0, out);
}

// round 13
// speedup vs baseline: 2.0331x; 1.5195x over previous
#include <cuda_runtime.h>
#include <cuda_fp16.h>

#define BATCH  128
#define TIME   256
#define FDIM   512
#define UNITS  1024
#define TP1    257
#define NCTA   64
#define NTHR   512

// ---- recurrent kernel smem layout (bytes) ----
#define WT_STRIDE 2064                 // 1024 fp16 + 16B pad (conflict-free ldmatrix)
#define SM_WTH    0
#define SM_WTL    (16 * WT_STRIDE)     // 33024
#define SM_P      (2 * 16 * WT_STRIDE) // 66048 (4 partial buffers x 8192 B)
#define SM_TOTALB (SM_P + 4 * 8192)    // 98816

// ---------------------------------------------------------------------------
// Global state in MMA fragment layout:
//   g_F[buf][ ((mt*64 + kt)*2 + part)*32 + lane ]  (uint4 = regs a0..a3)
//   mt: m-tile (16 batches), kt: k-tile (16 units), part: 0=hi 1=lo fp16.
// ---------------------------------------------------------------------------
__device__ __align__(256) uint4 g_F[2][8 * 64 * 2 * 32];   // 2 MB
__device__ unsigned g_cnt[8];
__device__ unsigned g_cnt2;
__device__ unsigned g_gen;

// ---------------------------------------------------------------------------
// PTX helpers (baseline ISA only — safe under compute_103 virtual arch)
// ---------------------------------------------------------------------------
__device__ __forceinline__ unsigned smem_u32(const void* p) {
    unsigned a;
    asm("{ .reg .u64 t; cvta.to.shared.u64 t, %1; cvt.u32.u64 %0, t; }"
        : "=r"(a) : "l"(p));
    return a;
}
__device__ __forceinline__ void ldm4(unsigned a, unsigned r[4]) {
    asm volatile("ldmatrix.sync.aligned.m8n8.x4.shared.b16 {%0,%1,%2,%3}, [%4];"
                 : "=r"(r[0]), "=r"(r[1]), "=r"(r[2]), "=r"(r[3]) : "r"(a));
}
__device__ __forceinline__ void mma_f16(float c[4], uint4 a,
                                        unsigned b0, unsigned b1) {
    asm volatile(
        "mma.sync.aligned.m16n8k16.row.col.f32.f16.f16.f32 "
        "{%0,%1,%2,%3}, {%4,%5,%6,%7}, {%8,%9}, {%0,%1,%2,%3};"
        : "+f"(c[0]), "+f"(c[1]), "+f"(c[2]), "+f"(c[3])
        : "r"(a.x), "r"(a.y), "r"(a.z), "r"(a.w), "r"(b0), "r"(b1));
}
__device__ __forceinline__ void ffma2(unsigned long long& d,
                                      unsigned long long a,
                                      unsigned long long b) {
    asm("fma.rn.f32x2 %0, %1, %2, %0;" : "+l"(d) : "l"(a), "l"(b));
}
__device__ __forceinline__ float2 u2f2(unsigned long long v) {
    float2 f;
    f.x = __uint_as_float((unsigned)(v & 0xffffffffu));
    f.y = __uint_as_float((unsigned)(v >> 32));
    return f;
}

// ---------------------------------------------------------------------------
// Hierarchical grid barrier over 64 CTAs (8 groups of 8).
// ---------------------------------------------------------------------------
__device__ __forceinline__ void gbar(unsigned& gen) {
    __syncthreads();
    if (threadIdx.x == 0) {
        __threadfence();
        int g = blockIdx.x >> 3;
        if (atomicAdd(&g_cnt[g], 1u) == 7u) {
            g_cnt[g] = 0u;
            __threadfence();
            if (atomicAdd(&g_cnt2, 1u) == 7u) {
                g_cnt2 = 0u;
                __threadfence();
                atomicAdd(&g_gen, 1u);
            }
        }
        while (*(volatile unsigned*)&g_gen == gen) { __nanosleep(20); }
        __threadfence();
    }
    __syncthreads();
    gen += 1u;
}

// ---------------------------------------------------------------------------
// Kernel A: h = inputs @ R + bias -> out[b, t, :]   (unchanged, passing)
// ---------------------------------------------------------------------------
#define ASTRIDE 132

__global__ void __launch_bounds__(256) hin_gemm_kernel(
    const float* __restrict__ X,
    const float* __restrict__ R,
    const float* __restrict__ bias,
    float* __restrict__ out)
{
    __shared__ float Asd[16 * ASTRIDE];
    __shared__ float Bs[16 * 64];

    const int tid  = threadIdx.x;
    const int tx   = tid & 15;
    const int ty   = tid >> 4;
    const int row0 = blockIdx.y * 64;
    const int col0 = blockIdx.x * 64;

    const int li = tid >> 2;
    const int lj = (tid & 3) * 4;
    const int rj = tid >> 4;
    const int ri = (tid & 15) * 4;

    unsigned long long cc[4][2];
    #pragma unroll
    for (int i = 0; i < 4; i++) { cc[i][0] = 0ULL; cc[i][1] = 0ULL; }

    float4 a = *(const float4*)(X + (size_t)(row0 + li) * FDIM + lj);
    float4 b = *(const float4*)(R + (size_t)rj * UNITS + col0 + ri);

    for (int k0 = 0; k0 < FDIM; k0 += 16) {
        *(float2*)(Asd + (lj + 0) * ASTRIDE + li * 2) = make_float2(a.x, a.x);
        *(float2*)(Asd + (lj + 1) * ASTRIDE + li * 2) = make_float2(a.y, a.y);
        *(float2*)(Asd + (lj + 2) * ASTRIDE + li * 2) = make_float2(a.z, a.z);
        *(float2*)(Asd + (lj + 3) * ASTRIDE + li * 2) = make_float2(a.w, a.w);
        *(float4*)(Bs + rj * 64 + ri) = b;
        __syncthreads();

        if (k0 + 16 < FDIM) {
            a = *(const float4*)(X + (size_t)(row0 + li) * FDIM + k0 + 16 + lj);
            b = *(const float4*)(R + (size_t)(k0 + 16 + rj) * UNITS + col0 + ri);
        }

        #pragma unroll
        for (int k = 0; k < 16; k++) {
            ulonglong2 a01 = *(const ulonglong2*)(Asd + k * ASTRIDE + ty * 8);
            ulonglong2 a23 = *(const ulonglong2*)(Asd + k * ASTRIDE + ty * 8 + 4);
            ulonglong2 bv  = *(const ulonglong2*)(Bs + k * 64 + tx * 4);
            ffma2(cc[0][0], a01.x, bv.x); ffma2(cc[0][1], a01.x, bv.y);
            ffma2(cc[1][0], a01.y, bv.x); ffma2(cc[1][1], a01.y, bv.y);
            ffma2(cc[2][0], a23.x, bv.x); ffma2(cc[2][1], a23.x, bv.y);
            ffma2(cc[3][0], a23.y, bv.x); ffma2(cc[3][1], a23.y, bv.y);
        }
        __syncthreads();
    }

    float4 bv = *(const float4*)(bias + col0 + tx * 4);
    #pragma unroll
    for (int i = 0; i < 4; i++) {
        int m    = row0 + ty * 4 + i;
        int bidx = m >> 8;
        int tt   = m & 255;
        float2 lo = u2f2(cc[i][0]);
        float2 hi = u2f2(cc[i][1]);
        float4 v;
        v.x = lo.x + bv.x; v.y = lo.y + bv.y;
        v.z = hi.x + bv.z; v.w = hi.y + bv.w;
        *(float4*)(out + ((size_t)(bidx * TP1 + tt)) * UNITS + col0 + tx * 4) = v;
    }
}

// ---------------------------------------------------------------------------
// Kernel B: persistent HMMA recurrence, fragment-resident state.
//   64 CTAs x 512 threads. CTA: units [u0,u0+16). 16 warps = 4 m-groups
//   (m32 each) x 4 k-quarters (k256 each). A fragments LDG'd straight from
//   g_F (no smem/ldmatrix/cp.async for A); W resident smem for B; 4-way
//   partial reduction; one syncthreads + one grid barrier per step.
// ---------------------------------------------------------------------------
__global__ void __launch_bounds__(NTHR) recurrent_kernel(
    const float* __restrict__ W,
    const float* __restrict__ x0,
    float* __restrict__ out)
{
    extern __shared__ __align__(128) char smem[];
    const unsigned sb = smem_u32(smem);
    const int tid = threadIdx.x;
    const int wid = tid >> 5;
    const int lid = tid & 31;
    const int u0  = blockIdx.x * 16;
    const int ktC = blockIdx.x;          // this CTA's k-tile for state writes

    // --- Convert W slice -> SMEM fp16 hi/lo, Wt[n][k], padded rows.
    for (int idx = tid; idx < 16 * UNITS; idx += NTHR) {
        int n = idx & 15;
        int k = idx >> 4;
        float v = __ldg(W + (size_t)k * UNITS + u0 + n);
        __half hi = __float2half_rn(v);
        __half lo = __float2half_rn(v - __half2float(hi));
        *(__half*)(smem + SM_WTH + n * WT_STRIDE + k * 2) = hi;
        *(__half*)(smem + SM_WTL + n * WT_STRIDE + k * 2) = lo;
    }

    // --- Epilogue / fragment-write mapping (thread -> batch er, 4 units ec..ec+3)
    const int er    = tid >> 2;          // batch 0..127
    const int ec    = (tid & 3) * 4;     // unit offset 0,4,8,12
    const int mtE   = er >> 4;
    const int rr    = er & 15;
    const int laneA = (rr & 7) * 4 + ((ec >> 1) & 3);
    const int regE  = (rr >> 3) + 2 * (ec >> 3);
    const unsigned fragBaseRel = (unsigned)(((mtE * 64 + ktC) * 2) * 32);

    // --- Init state buffer 0 with x0 (fragment layout, this CTA's kt).
    {
        unsigned* fb = (unsigned*)(g_F[0] + fragBaseRel);
        #pragma unroll
        for (int j = 0; j < 2; j++) {          // unit pairs (ec+2j, ec+2j+1)
            float v0 = x0[u0 + ec + 2 * j];
            float v1 = x0[u0 + ec + 2 * j + 1];
            __half h0 = __float2half_rn(v0);
            __half h1 = __float2half_rn(v1);
            __half l0 = __float2half_rn(v0 - __half2float(h0));
            __half l1 = __float2half_rn(v1 - __half2float(h1));
            unsigned pH = (unsigned)__half_as_ushort(h0)
                        | ((unsigned)__half_as_ushort(h1) << 16);
            unsigned pL = (unsigned)__half_as_ushort(l0)
                        | ((unsigned)__half_as_ushort(l1) << 16);
            fb[(laneA + j) * 4 + regE]       = pH;
            fb[128 + (laneA + j) * 4 + regE] = pL;   // part 1 = +32 uint4
        }
    }
    __threadfence();

    unsigned gen = *(volatile unsigned*)&g_gen;
    gbar(gen);

    // --- MMA warp mapping: mg = m-group (m32), kh = k-quarter (k256).
    const int mg  = wid & 3;
    const int kh  = wid >> 2;
    const int rb  = mg * 32;
    const int mt0 = mg * 2;
    // B ldmatrix lane addressing (verified R9 pattern).
    const int b_n    = (lid & 7) | ((lid >> 1) & 8);
    const int b_koff = ((lid >> 3) & 1) * 16;
    const unsigned bofl = (unsigned)(b_n * WT_STRIDE + b_koff);

    const size_t outbase = ((size_t)er * TP1) * UNITS + u0 + ec;

    float es[4] = {0.f, 0.f, 0.f, 0.f};
    int cur = 0;

    for (int t = 0; t < TIME; t++) {
        // h_t prefetch (covered by the k-loop).
        float4 h = __ldg((const float4*)(out + outbase + (size_t)t * UNITS));

        float acc[2][2][4];
        #pragma unroll
        for (int mi = 0; mi < 2; mi++)
            #pragma unroll
            for (int ni = 0; ni < 2; ni++)
                #pragma unroll
                for (int q = 0; q < 4; q++) acc[mi][ni][q] = 0.0f;

        const uint4* F = g_F[cur];
        // f[q*4 + {mt0 hi, mt0 lo, mt1 hi, mt1 lo}] for 2 k-tiles per stage
        uint4 f[8];
        {
            int kt = kh * 16;
            const uint4* p0 = F + mt0 * 4096 + kt * 64 + lid;
            const uint4* p1 = p0 + 4096;
            f[0] = __ldcg(p0);       f[1] = __ldcg(p0 + 32);
            f[2] = __ldcg(p1);       f[3] = __ldcg(p1 + 32);
            f[4] = __ldcg(p0 + 64);  f[5] = __ldcg(p0 + 96);
            f[6] = __ldcg(p1 + 64);  f[7] = __ldcg(p1 + 96);
        }

        for (int sc = 0; sc < 8; sc++) {
            uint4 nf[8];
            if (sc < 7) {
                int kt = kh * 16 + sc * 2 + 2;
                const uint4* p0 = F + mt0 * 4096 + kt * 64 + lid;
                const uint4* p1 = p0 + 4096;
                nf[0] = __ldcg(p0);       nf[1] = __ldcg(p0 + 32);
                nf[2] = __ldcg(p1);       nf[3] = __ldcg(p1 + 32);
                nf[4] = __ldcg(p0 + 64);  nf[5] = __ldcg(p0 + 96);
                nf[6] = __ldcg(p1 + 64);  nf[7] = __ldcg(p1 + 96);
            }

            #pragma unroll
            for (int q = 0; q < 2; q++) {
                int kt = kh * 16 + sc * 2 + q;
                unsigned bh[4], bl[4];
                ldm4(sb + SM_WTH + bofl + (unsigned)(kt * 32), bh);
                ldm4(sb + SM_WTL + bofl + (unsigned)(kt * 32), bl);

                uint4 ah0 = f[q * 4 + 0], al0 = f[q * 4 + 1];
                uint4 ah1 = f[q * 4 + 2], al1 = f[q * 4 + 3];

                mma_f16(acc[0][0], ah0, bh[0], bh[1]);
                mma_f16(acc[0][1], ah0, bh[2], bh[3]);
                mma_f16(acc[1][0], ah1, bh[0], bh[1]);
                mma_f16(acc[1][1], ah1, bh[2], bh[3]);
                mma_f16(acc[0][0], ah0, bl[0], bl[1]);
                mma_f16(acc[0][1], ah0, bl[2], bl[3]);
                mma_f16(acc[1][0], ah1, bl[0], bl[1]);
                mma_f16(acc[1][1], ah1, bl[2], bl[3]);
                mma_f16(acc[0][0], al0, bh[0], bh[1]);
                mma_f16(acc[0][1], al0, bh[2], bh[3]);
                mma_f16(acc[1][0], al1, bh[0], bh[1]);
                mma_f16(acc[1][1], al1, bh[2], bh[3]);
            }

            if (sc < 7) {
                #pragma unroll
                for (int i = 0; i < 8; i++) f[i] = nf[i];
            }
        }

        // --- store k-quarter partials
        {
            float* P = (float*)(smem + SM_P + kh * 8192);
            int pr = rb + (lid >> 2);
            int pc = (lid & 3) * 2;
            #pragma unroll
            for (int mi = 0; mi < 2; mi++)
                #pragma unroll
                for (int ni = 0; ni < 2; ni++) {
                    int base = (pr + mi * 16) * 16 + ni * 8 + pc;
                    *(float2*)(P + base) =
                        make_float2(acc[mi][ni][0], acc[mi][ni][1]);
                    *(float2*)(P + base + 128) =
                        make_float2(acc[mi][ni][2], acc[mi][ni][3]);
                }
        }
        __syncthreads();

        // --- epilogue: reduce 4 quarters, tanh, exp, write out + state frags
        {
            const float* P0 = (const float*)(smem + SM_P) + er * 16 + ec;
            float4 p0 = *(const float4*)P0;
            float4 p1 = *(const float4*)(P0 + 2048);
            float4 p2 = *(const float4*)(P0 + 4096);
            float4 p3 = *(const float4*)(P0 + 6144);

            float s[4];
            s[0] = tanhf(h.x + ((p0.x + p1.x) + (p2.x + p3.x)));
            s[1] = tanhf(h.y + ((p0.y + p1.y) + (p2.y + p3.y)));
            s[2] = tanhf(h.z + ((p0.z + p1.z) + (p2.z + p3.z)));
            s[3] = tanhf(h.w + ((p0.w + p1.w) + (p2.w + p3.w)));

            *(float4*)(out + outbase + (size_t)t * UNITS)
                = make_float4(s[0], s[1], s[2], s[3]);

            unsigned* fb = (unsigned*)(g_F[cur ^ 1] + fragBaseRel);
            #pragma unroll
            for (int j = 0; j < 2; j++) {
                float v0 = s[2 * j], v1 = s[2 * j + 1];
                __half h0v = __float2half_rn(v0);
                __half h1v = __float2half_rn(v1);
                __half l0v = __float2half_rn(v0 - __half2float(h0v));
                __half l1v = __float2half_rn(v1 - __half2float(h1v));
                unsigned pH = (unsigned)__half_as_ushort(h0v)
                            | ((unsigned)__half_as_ushort(h1v) << 16);
                unsigned pL = (unsigned)__half_as_ushort(l0v)
                            | ((unsigned)__half_as_ushort(l1v) << 16);
                fb[(laneA + j) * 4 + regE]       = pH;
                fb[128 + (laneA + j) * 4 + regE] = pL;
            }

            es[0] += __expf(s[0]);
            es[1] += __expf(s[1]);
            es[2] += __expf(s[2]);
            es[3] += __expf(s[3]);
        }

        cur ^= 1;
        gbar(gen);   // publishes state frags; also separates P reuse
    }

    // --- terminal row: (1/beta) log(tanh(mean_t exp(beta*s))), beta=1
    {
        const float inv = 1.0f / (float)TIME;
        float4 tm;
        tm.x = logf(tanhf(es[0] * inv));
        tm.y = logf(tanhf(es[1] * inv));
        tm.z = logf(tanhf(es[2] * inv));
        tm.w = logf(tanhf(es[3] * inv));
        *(float4*)(out + outbase + (size_t)TIME * UNITS) = tm;
    }
}

// ---------------------------------------------------------------------------
// Launch
// ---------------------------------------------------------------------------
extern "C" void kernel_launch(void* const* d_in, const int* in_sizes, int n_in,
                              void* d_out, int out_size) {
    const float* X    = (const float*)d_in[0];  // [128,256,512]
    const float* R    = (const float*)d_in[1];  // [512,1024]
    const float* W    = (const float*)d_in[2];  // [1024,1024]
    const float* bias = (const float*)d_in[3];  // [1024]
    const float* x0   = (const float*)d_in[4];  // [1024]
    float* out = (float*)d_out;                 // [128,257,1024]

    (void)in_sizes; (void)n_in; (void)out_size;

    dim3 gridA(UNITS / 64, (BATCH * TIME) / 64);
    hin_gemm_kernel<<<gridA, 256>>>(X, R, bias, out);

    cudaFuncSetAttribute(recurrent_kernel,
                         cudaFuncAttributeMaxDynamicSharedMemorySize, SM_TOTALB);
    recurrent_kernel<<<NCTA, NTHR, SM_TOTALB>>>(W, x0, out);
}

// round 15
// speedup vs baseline: 2.9074x; 1.4301x over previous
#include <cuda_runtime.h>
#include <cuda_fp16.h>

#define BATCH  128
#define TIME   256
#define FDIM   512
#define UNITS  1024
#define TP1    257
#define NRCTA  64          // recurrence CTAs
#define NGCTA  84          // GEMM CTAs
#define NCTA   (NRCTA + NGCTA)
#define NTHR   512

// ---- recurrence smem layout (bytes) ----
#define WT_STRIDE 2064                 // 1024 fp16 + 16B pad (conflict-free ldmatrix)
#define SM_WTH    0
#define SM_WTL    (16 * WT_STRIDE)     // 33024
#define SM_P      (2 * 16 * WT_STRIDE) // 66048 (4 partial buffers x 8192 B)
#define SM_TOTALB (SM_P + 4 * 8192)    // 98816  (GEMM path uses < 17KB of this)

// ---------------------------------------------------------------------------
// Global state in MMA fragment layout:
//   g_F[buf][ ((mt*64 + kt)*2 + part)*32 + lane ]  (uint4 = regs a0..a3)
// ---------------------------------------------------------------------------
__device__ __align__(256) uint4 g_F[2][8 * 64 * 2 * 32];   // 2 MB
__device__ unsigned g_cnt[8];
__device__ unsigned g_cnt2;
__device__ unsigned g_gen;
__device__ unsigned g_hcnt[TIME];   // per-timestep h readiness (16 tiles each)

// ---------------------------------------------------------------------------
// PTX helpers (baseline ISA only — safe under compute_103 virtual arch)
// ---------------------------------------------------------------------------
__device__ __forceinline__ unsigned smem_u32(const void* p) {
    unsigned a;
    asm("{ .reg .u64 t; cvta.to.shared.u64 t, %1; cvt.u32.u64 %0, t; }"
        : "=r"(a) : "l"(p));
    return a;
}
__device__ __forceinline__ void ldm4(unsigned a, unsigned r[4]) {
    asm volatile("ldmatrix.sync.aligned.m8n8.x4.shared.b16 {%0,%1,%2,%3}, [%4];"
                 : "=r"(r[0]), "=r"(r[1]), "=r"(r[2]), "=r"(r[3]) : "r"(a));
}
__device__ __forceinline__ void mma_f16(float c[4], uint4 a,
                                        unsigned b0, unsigned b1) {
    asm volatile(
        "mma.sync.aligned.m16n8k16.row.col.f32.f16.f16.f32 "
        "{%0,%1,%2,%3}, {%4,%5,%6,%7}, {%8,%9}, {%0,%1,%2,%3};"
        : "+f"(c[0]), "+f"(c[1]), "+f"(c[2]), "+f"(c[3])
        : "r"(a.x), "r"(a.y), "r"(a.z), "r"(a.w), "r"(b0), "r"(b1));
}
__device__ __forceinline__ void ffma2(unsigned long long& d,
                                      unsigned long long a,
                                      unsigned long long b) {
    asm("fma.rn.f32x2 %0, %1, %2, %0;" : "+l"(d) : "l"(a), "l"(b));
}
__device__ __forceinline__ float2 u2f2(unsigned long long v) {
    float2 f;
    f.x = __uint_as_float((unsigned)(v & 0xffffffffu));
    f.y = __uint_as_float((unsigned)(v >> 32));
    return f;
}
// Fast tanh: 1 - 2/(e^{2x}+1).  __expf rel err ~2^-22; stable at both tails.
__device__ __forceinline__ float ftanh(float x) {
    float e = __expf(2.0f * x);
    return 1.0f - __fdividef(2.0f, e + 1.0f);
}

// ---------------------------------------------------------------------------
// Grid barrier over the 64 recurrence CTAs (8 groups of 8), with optional
// h-readiness poll for the next timestep folded into the spin.
// ---------------------------------------------------------------------------
__device__ __forceinline__ void gbar(unsigned& gen, int tpoll) {
    __syncthreads();
    if (threadIdx.x == 0) {
        __threadfence();
        int g = blockIdx.x >> 3;
        if (atomicAdd(&g_cnt[g], 1u) == 7u) {
            g_cnt[g] = 0u;
            __threadfence();
            if (atomicAdd(&g_cnt2, 1u) == 7u) {
                g_cnt2 = 0u;
                __threadfence();
                atomicAdd(&g_gen, 1u);
            }
        }
        while (*(volatile unsigned*)&g_gen == gen) { __nanosleep(20); }
        if (tpoll >= 0)
            while (*(volatile unsigned*)&g_hcnt[tpoll] < 16u) { __nanosleep(20); }
        __threadfence();
    }
    __syncthreads();
    gen += 1u;
}

// ---------------------------------------------------------------------------
// Reset kernel: zero per-launch counters (graph-replay determinism).
// ---------------------------------------------------------------------------
__global__ void reset_kernel() {
    if (threadIdx.x < TIME) g_hcnt[threadIdx.x] = 0u;
}

// ---------------------------------------------------------------------------
// GEMM body (CTAs 64..147): h = X@R + bias -> out[b][t][:], t-major tiles.
// Tile: 64 m-rows (one t, half the batch) x 128 n-cols, BK=16, 512 threads,
// thread tile 4x4, FFMA2. After each tile: release-fence + g_hcnt[t]++.
// ---------------------------------------------------------------------------
#define ASTRIDE 132

__device__ void gemm_body(const float* __restrict__ X,
                          const float* __restrict__ R,
                          const float* __restrict__ bias,
                          float* __restrict__ out,
                          char* smem, int cid)
{
    float* Asd = (float*)smem;               // [16][132] duplicated A
    float* Bs  = (float*)smem + 16 * ASTRIDE; // [16][128]

    const int tid = threadIdx.x;
    const int tx  = tid & 31;       // n quad
    const int ty  = tid >> 5;       // m quad (0..15)
    const int li  = tid >> 2;       // A row (tid<256)
    const int lj  = (tid & 3) * 4;  // A k offset
    const int rj  = tid >> 5;       // B k row (0..15)
    const int ri  = (tid & 31) * 4; // B col

    for (int tau = cid; tau < 4096; tau += NGCTA) {
        const int t    = tau >> 4;
        const int sub  = tau & 15;
        const int bb0  = (sub & 1) * 64;
        const int col0 = (sub >> 1) * 128;

        unsigned long long cc[4][2];
        #pragma unroll
        for (int i = 0; i < 4; i++) { cc[i][0] = 0ULL; cc[i][1] = 0ULL; }

        const float* Xrow = X + ((size_t)(bb0 + li) * TIME + t) * FDIM;
        float4 a, b;
        if (tid < 256) a = *(const float4*)(Xrow + lj);
        b = *(const float4*)(R + (size_t)rj * UNITS + col0 + ri);

        for (int k0 = 0; k0 < FDIM; k0 += 16) {
            if (tid < 256) {
                *(float2*)(Asd + (lj + 0) * ASTRIDE + li * 2) = make_float2(a.x, a.x);
                *(float2*)(Asd + (lj + 1) * ASTRIDE + li * 2) = make_float2(a.y, a.y);
                *(float2*)(Asd + (lj + 2) * ASTRIDE + li * 2) = make_float2(a.z, a.z);
                *(float2*)(Asd + (lj + 3) * ASTRIDE + li * 2) = make_float2(a.w, a.w);
            }
            *(float4*)(Bs + rj * 128 + ri) = b;
            __syncthreads();

            if (k0 + 16 < FDIM) {
                if (tid < 256) a = *(const float4*)(Xrow + k0 + 16 + lj);
                b = *(const float4*)(R + (size_t)(k0 + 16 + rj) * UNITS + col0 + ri);
            }

            #pragma unroll
            for (int k = 0; k < 16; k++) {
                ulonglong2 a01 = *(const ulonglong2*)(Asd + k * ASTRIDE + ty * 8);
                ulonglong2 a23 = *(const ulonglong2*)(Asd + k * ASTRIDE + ty * 8 + 4);
                ulonglong2 bv  = *(const ulonglong2*)(Bs + k * 128 + tx * 4);
                ffma2(cc[0][0], a01.x, bv.x); ffma2(cc[0][1], a01.x, bv.y);
                ffma2(cc[1][0], a01.y, bv.x); ffma2(cc[1][1], a01.y, bv.y);
                ffma2(cc[2][0], a23.x, bv.x); ffma2(cc[2][1], a23.x, bv.y);
                ffma2(cc[3][0], a23.y, bv.x); ffma2(cc[3][1], a23.y, bv.y);
            }
            __syncthreads();
        }

        float4 bv4 = __ldg((const float4*)(bias + col0 + tx * 4));
        #pragma unroll
        for (int i = 0; i < 4; i++) {
            int bb = bb0 + ty * 4 + i;
            float2 lo = u2f2(cc[i][0]);
            float2 hi = u2f2(cc[i][1]);
            float4 v;
            v.x = lo.x + bv4.x; v.y = lo.y + bv4.y;
            v.z = hi.x + bv4.z; v.w = hi.y + bv4.w;
            *(float4*)(out + ((size_t)bb * TP1 + t) * UNITS + col0 + tx * 4) = v;
        }
        __syncthreads();
        if (tid == 0) {
            __threadfence();
            atomicAdd(&g_hcnt[t], 1u);
        }
    }
}

// ---------------------------------------------------------------------------
// Recurrence body (CTAs 0..63): persistent HMMA, fragment-resident state.
// (verified R13 structure; edits: ftanh, h-poll in gbar, no final barrier)
// ---------------------------------------------------------------------------
__device__ void recur_body(const float* __restrict__ W,
                           const float* __restrict__ x0,
                           float* __restrict__ out,
                           char* smem)
{
    const unsigned sb = smem_u32(smem);
    const int tid = threadIdx.x;
    const int wid = tid >> 5;
    const int lid = tid & 31;
    const int u0  = blockIdx.x * 16;
    const int ktC = blockIdx.x;

    // W slice -> SMEM fp16 hi/lo, Wt[n][k], padded rows.
    for (int idx = tid; idx < 16 * UNITS; idx += NTHR) {
        int n = idx & 15;
        int k = idx >> 4;
        float v = __ldg(W + (size_t)k * UNITS + u0 + n);
        __half hi = __float2half_rn(v);
        __half lo = __float2half_rn(v - __half2float(hi));
        *(__half*)(smem + SM_WTH + n * WT_STRIDE + k * 2) = hi;
        *(__half*)(smem + SM_WTL + n * WT_STRIDE + k * 2) = lo;
    }

    // Epilogue / fragment-write mapping.
    const int er    = tid >> 2;
    const int ec    = (tid & 3) * 4;
    const int mtE   = er >> 4;
    const int rr    = er & 15;
    const int laneA = (rr & 7) * 4 + ((ec >> 1) & 3);
    const int regE  = (rr >> 3) + 2 * (ec >> 3);
    const unsigned fragBaseRel = (unsigned)(((mtE * 64 + ktC) * 2) * 32);

    // Init state buffer 0 with x0 (fragment layout).
    {
        unsigned* fb = (unsigned*)(g_F[0] + fragBaseRel);
        #pragma unroll
        for (int j = 0; j < 2; j++) {
            float v0 = x0[u0 + ec + 2 * j];
            float v1 = x0[u0 + ec + 2 * j + 1];
            __half h0 = __float2half_rn(v0);
            __half h1 = __float2half_rn(v1);
            __half l0 = __float2half_rn(v0 - __half2float(h0));
            __half l1 = __float2half_rn(v1 - __half2float(h1));
            unsigned pH = (unsigned)__half_as_ushort(h0)
                        | ((unsigned)__half_as_ushort(h1) << 16);
            unsigned pL = (unsigned)__half_as_ushort(l0)
                        | ((unsigned)__half_as_ushort(l1) << 16);
            fb[(laneA + j) * 4 + regE]       = pH;
            fb[128 + (laneA + j) * 4 + regE] = pL;
        }
    }
    __threadfence();

    unsigned gen = *(volatile unsigned*)&g_gen;
    gbar(gen, 0);          // also waits for h_0 readiness

    const int mg  = wid & 3;
    const int kh  = wid >> 2;
    const int rb  = mg * 32;
    const int mt0 = mg * 2;
    const int b_n    = (lid & 7) | ((lid >> 1) & 8);
    const int b_koff = ((lid >> 3) & 1) * 16;
    const unsigned bofl = (unsigned)(b_n * WT_STRIDE + b_koff);

    const size_t outbase = ((size_t)er * TP1) * UNITS + u0 + ec;

    float es[4] = {0.f, 0.f, 0.f, 0.f};
    int cur = 0;

    for (int t = 0; t < TIME; t++) {
        float4 h = __ldg((const float4*)(out + outbase + (size_t)t * UNITS));

        float acc[2][2][4];
        #pragma unroll
        for (int mi = 0; mi < 2; mi++)
            #pragma unroll
            for (int ni = 0; ni < 2; ni++)
                #pragma unroll
                for (int q = 0; q < 4; q++) acc[mi][ni][q] = 0.0f;

        const uint4* F = g_F[cur];
        uint4 f[8];
        {
            int kt = kh * 16;
            const uint4* p0 = F + mt0 * 4096 + kt * 64 + lid;
            const uint4* p1 = p0 + 4096;
            f[0] = __ldcg(p0);       f[1] = __ldcg(p0 + 32);
            f[2] = __ldcg(p1);       f[3] = __ldcg(p1 + 32);
            f[4] = __ldcg(p0 + 64);  f[5] = __ldcg(p0 + 96);
            f[6] = __ldcg(p1 + 64);  f[7] = __ldcg(p1 + 96);
        }

        for (int sc = 0; sc < 8; sc++) {
            uint4 nf[8];
            if (sc < 7) {
                int kt = kh * 16 + sc * 2 + 2;
                const uint4* p0 = F + mt0 * 4096 + kt * 64 + lid;
                const uint4* p1 = p0 + 4096;
                nf[0] = __ldcg(p0);       nf[1] = __ldcg(p0 + 32);
                nf[2] = __ldcg(p1);       nf[3] = __ldcg(p1 + 32);
                nf[4] = __ldcg(p0 + 64);  nf[5] = __ldcg(p0 + 96);
                nf[6] = __ldcg(p1 + 64);  nf[7] = __ldcg(p1 + 96);
            }

            #pragma unroll
            for (int q = 0; q < 2; q++) {
                int kt = kh * 16 + sc * 2 + q;
                unsigned bh[4], bl[4];
                ldm4(sb + SM_WTH + bofl + (unsigned)(kt * 32), bh);
                ldm4(sb + SM_WTL + bofl + (unsigned)(kt * 32), bl);

                uint4 ah0 = f[q * 4 + 0], al0 = f[q * 4 + 1];
                uint4 ah1 = f[q * 4 + 2], al1 = f[q * 4 + 3];

                mma_f16(acc[0][0], ah0, bh[0], bh[1]);
                mma_f16(acc[0][1], ah0, bh[2], bh[3]);
                mma_f16(acc[1][0], ah1, bh[0], bh[1]);
                mma_f16(acc[1][1], ah1, bh[2], bh[3]);
                mma_f16(acc[0][0], ah0, bl[0], bl[1]);
                mma_f16(acc[0][1], ah0, bl[2], bl[3]);
                mma_f16(acc[1][0], ah1, bl[0], bl[1]);
                mma_f16(acc[1][1], ah1, bl[2], bl[3]);
                mma_f16(acc[0][0], al0, bh[0], bh[1]);
                mma_f16(acc[0][1], al0, bh[2], bh[3]);
                mma_f16(acc[1][0], al1, bh[0], bh[1]);
                mma_f16(acc[1][1], al1, bh[2], bh[3]);
            }

            if (sc < 7) {
                #pragma unroll
                for (int i = 0; i < 8; i++) f[i] = nf[i];
            }
        }

        // store k-quarter partials
        {
            float* P = (float*)(smem + SM_P + kh * 8192);
            int pr = rb + (lid >> 2);
            int pc = (lid & 3) * 2;
            #pragma unroll
            for (int mi = 0; mi < 2; mi++)
                #pragma unroll
                for (int ni = 0; ni < 2; ni++) {
                    int base = (pr + mi * 16) * 16 + ni * 8 + pc;
                    *(float2*)(P + base) =
                        make_float2(acc[mi][ni][0], acc[mi][ni][1]);
                    *(float2*)(P + base + 128) =
                        make_float2(acc[mi][ni][2], acc[mi][ni][3]);
                }
        }
        __syncthreads();

        // epilogue
        {
            const float* P0 = (const float*)(smem + SM_P) + er * 16 + ec;
            float4 p0 = *(const float4*)P0;
            float4 p1 = *(const float4*)(P0 + 2048);
            float4 p2 = *(const float4*)(P0 + 4096);
            float4 p3 = *(const float4*)(P0 + 6144);

            float s[4];
            s[0] = ftanh(h.x + ((p0.x + p1.x) + (p2.x + p3.x)));
            s[1] = ftanh(h.y + ((p0.y + p1.y) + (p2.y + p3.y)));
            s[2] = ftanh(h.z + ((p0.z + p1.z) + (p2.z + p3.z)));
            s[3] = ftanh(h.w + ((p0.w + p1.w) + (p2.w + p3.w)));

            unsigned* fb = (unsigned*)(g_F[cur ^ 1] + fragBaseRel);
            #pragma unroll
            for (int j = 0; j < 2; j++) {
                float v0 = s[2 * j], v1 = s[2 * j + 1];
                __half h0v = __float2half_rn(v0);
                __half h1v = __float2half_rn(v1);
                __half l0v = __float2half_rn(v0 - __half2float(h0v));
                __half l1v = __float2half_rn(v1 - __half2float(h1v));
                unsigned pH = (unsigned)__half_as_ushort(h0v)
                            | ((unsigned)__half_as_ushort(h1v) << 16);
                unsigned pL = (unsigned)__half_as_ushort(l0v)
                            | ((unsigned)__half_as_ushort(l1v) << 16);
                fb[(laneA + j) * 4 + regE]       = pH;
                fb[128 + (laneA + j) * 4 + regE] = pL;
            }

            *(float4*)(out + outbase + (size_t)t * UNITS)
                = make_float4(s[0], s[1], s[2], s[3]);

            es[0] += __expf(s[0]);
            es[1] += __expf(s[1]);
            es[2] += __expf(s[2]);
            es[3] += __expf(s[3]);
        }

        cur ^= 1;
        if (t + 1 < TIME) gbar(gen, t + 1);
    }

    // terminal row
    {
        const float inv = 1.0f / (float)TIME;
        float4 tm;
        tm.x = logf(tanhf(es[0] * inv));
        tm.y = logf(tanhf(es[1] * inv));
        tm.z = logf(tanhf(es[2] * inv));
        tm.w = logf(tanhf(es[3] * inv));
        *(float4*)(out + outbase + (size_t)TIME * UNITS) = tm;
    }
}

// ---------------------------------------------------------------------------
// Fused kernel: CTAs 0..63 recurrence, 64..147 h-projection GEMM.
// ---------------------------------------------------------------------------
__global__ void __launch_bounds__(NTHR) fused_kernel(
    const float* __restrict__ X,
    const float* __restrict__ R,
    const float* __restrict__ W,
    const float* __restrict__ bias,
    const float* __restrict__ x0,
    float* __restrict__ out)
{
    extern __shared__ __align__(128) char smem[];
    if (blockIdx.x < NRCTA) {
        recur_body(W, x0, out, smem);
    } else {
        gemm_body(X, R, bias, out, smem, blockIdx.x - NRCTA);
    }
}

// ---------------------------------------------------------------------------
// Launch
// ---------------------------------------------------------------------------
extern "C" void kernel_launch(void* const* d_in, const int* in_sizes, int n_in,
                              void* d_out, int out_size) {
    const float* X    = (const float*)d_in[0];  // [128,256,512]
    const float* R    = (const float*)d_in[1];  // [512,1024]
    const float* W    = (const float*)d_in[2];  // [1024,1024]
    const float* bias = (const float*)d_in[3];  // [1024]
    const float* x0   = (const float*)d_in[4];  // [1024]
    float* out = (float*)d_out;                 // [128,257,1024]

    (void)in_sizes; (void)n_in; (void)out_size;

    reset_kernel<<<1, 256>>>();

    cudaFuncSetAttribute(fused_kernel,
                         cudaFuncAttributeMaxDynamicSharedMemorySize, SM_TOTALB);
    fused_kernel<<<NCTA, NTHR, SM_TOTALB>>>(X, R, W, bias, x0, out);
}